// round 2
// baseline (speedup 1.0000x reference)
#include <cuda_runtime.h>
#include <math.h>

#define NN 50000
#define DD 128
#define EE 400000
#define NE (NN*DD)

// ---------------- scratch (static device memory; no allocations) ----------
__device__ __align__(16) float g_emb[4*NE];      // embeddings; later reused as f-buffer
__device__ __align__(16) float g_h[4*NE];        // GEMM output h; later reused as attention o
__device__ __align__(16) float g_agg[4*NE];      // aggregation; final embeddings live here
__device__ __align__(16) float g_qkv[4ll*NN*384];
__device__ __align__(16) float g_dinv[4*NN];     // deg then rsqrt(deg)
__device__ __align__(16) float g_rels[2][4*DD];  // ping-pong relation embeddings
__device__ __align__(16) float g_stats[4*DD*2];  // BN sum/sumsq
__device__ __align__(16) float g_bnp[4*DD*2];    // BN scale/shift
__device__ float g_score[4];
__device__ float g_w[4];

// perm: processing order (n,poi,s,d) <- rel_emb/edge index (j+3)&3

// ---------------- init kernels --------------------------------------------
__global__ void k_init_emb(const float* __restrict__ feat) {
    int i = blockIdx.x * blockDim.x + threadIdx.x;
    if (i < NE) {
        float v = feat[i];
        g_emb[i] = v; g_emb[NE + i] = v; g_emb[2*NE + i] = v; g_emb[3*NE + i] = v;
    }
}

__global__ void k_init_small(const float* __restrict__ rel_emb) {
    int i = blockIdx.x * blockDim.x + threadIdx.x;
    if (i < 4*NN) g_dinv[i] = 1.0f;           // deg starts at 1 (self loop)
    if (i < 4*DD) {
        int j = i >> 7, c = i & 127;
        int p = (j + 3) & 3;
        g_rels[0][i] = rel_emb[p*DD + c];
    }
    if (i < 4) g_score[i] = 0.0f;
}

__global__ void k_deg(const int* __restrict__ ei) {
    int t = blockIdx.x * blockDim.x + threadIdx.x;
    if (t >= 4*EE) return;
    int j = t / EE; int e = t - j*EE;
    int p = (j + 3) & 3;
    int dst = ei[(size_t)p*2*EE + EE + e];
    atomicAdd(&g_dinv[j*NN + dst], 1.0f);
}

__global__ void k_rsqrt_deg() {
    int i = blockIdx.x * blockDim.x + threadIdx.x;
    if (i < 4*NN) g_dinv[i] = rsqrtf(g_dinv[i]);
}

// ---------------- GCN GEMM: h = (emb*rels) @ W ; agg = h*dinv^2 + b --------
// block 256 = 8 warps; BM=64 rows; each warp 8 rows, each lane 4 cols.
__global__ __launch_bounds__(256) void k_gcn_gemm(
    const float* __restrict__ Wg, const float* __restrict__ bg,
    const float* __restrict__ rels)
{
    extern __shared__ float sm[];
    float* Wsm = sm;               // 128*128
    float* Xsm = sm + 128*128;     // 64*128
    int j = blockIdx.y;
    int r0 = blockIdx.x * 64;
    int tid = threadIdx.x;

    for (int e = tid; e < 128*128; e += 256) Wsm[e] = Wg[e];
    const float* rrow = rels + j*DD;
    for (int e = tid; e < 64*128; e += 256) {
        int r = e >> 7, k = e & 127;
        int gr = r0 + r;
        Xsm[e] = (gr < NN) ? g_emb[((size_t)j*NN + gr)*DD + k] * __ldg(&rrow[k]) : 0.0f;
    }
    __syncthreads();

    int wid = tid >> 5, lane = tid & 31;
    float acc[8][4];
#pragma unroll
    for (int r = 0; r < 8; r++) { acc[r][0]=0.f; acc[r][1]=0.f; acc[r][2]=0.f; acc[r][3]=0.f; }
    const float* xb = Xsm + (wid*8)*128;
#pragma unroll 4
    for (int k = 0; k < 128; k++) {
        float4 wv = *(const float4*)&Wsm[k*128 + lane*4];
#pragma unroll
        for (int r = 0; r < 8; r++) {
            float xv = xb[r*128 + k];
            acc[r][0] += xv*wv.x; acc[r][1] += xv*wv.y;
            acc[r][2] += xv*wv.z; acc[r][3] += xv*wv.w;
        }
    }
    float4 b4 = *(const float4*)&bg[lane*4];
#pragma unroll
    for (int r = 0; r < 8; r++) {
        int gr = r0 + wid*8 + r;
        if (gr < NN) {
            size_t off = ((size_t)j*NN + gr)*DD + lane*4;
            float4 h4 = make_float4(acc[r][0], acc[r][1], acc[r][2], acc[r][3]);
            *(float4*)&g_h[off] = h4;
            float di = __ldg(&g_dinv[j*NN + gr]); float d2 = di*di;
            float4 a4 = make_float4(h4.x*d2 + b4.x, h4.y*d2 + b4.y,
                                    h4.z*d2 + b4.z, h4.w*d2 + b4.w);
            *(float4*)&g_agg[off] = a4;
        }
    }
}

// ---------------- edge scatter: agg[dst] += h[src]*norm --------------------
__global__ __launch_bounds__(256) void k_scatter(const int* __restrict__ ei) {
    int j = blockIdx.y;
    int wid = threadIdx.x >> 5, lane = threadIdx.x & 31;
    long e = (long)blockIdx.x*8 + wid;
    if (e >= EE) return;
    int p = (j + 3) & 3;
    const int* base = ei + (size_t)p*2*EE;
    int src = __ldg(&base[e]);
    int dst = __ldg(&base[EE + e]);
    float norm = __ldg(&g_dinv[j*NN + src]) * __ldg(&g_dinv[j*NN + dst]);
    float4 h4 = *(const float4*)&g_h[((size_t)j*NN + src)*DD + lane*4];
    float* ap = &g_agg[((size_t)j*NN + dst)*DD + lane*4];
    atomicAdd(ap + 0, h4.x*norm);
    atomicAdd(ap + 1, h4.y*norm);
    atomicAdd(ap + 2, h4.z*norm);
    atomicAdd(ap + 3, h4.w*norm);
}

// ---------------- BatchNorm ------------------------------------------------
__global__ void k_zero_stats() { int i = threadIdx.x; if (i < 4*DD*2) g_stats[i] = 0.f; }

__global__ void k_bn_stats(int chunk) {
    int j = blockIdx.y, c = threadIdx.x;
    int rs = blockIdx.x * chunk;
    int re = min(rs + chunk, NN);
    float s = 0.f, s2 = 0.f;
    const float* base = g_agg + (size_t)j*NE;
    for (int r = rs; r < re; r++) {
        float v = base[(size_t)r*DD + c];
        s += v; s2 += v*v;
    }
    atomicAdd(&g_stats[(j*DD + c)*2], s);
    atomicAdd(&g_stats[(j*DD + c)*2 + 1], s2);
}

__global__ void k_bn_finalize(const float* __restrict__ gamma, const float* __restrict__ beta) {
    int i = threadIdx.x;
    if (i < 4*DD) {
        int c = i & 127;
        float s = g_stats[i*2], s2 = g_stats[i*2 + 1];
        float mean = s / (float)NN;
        float var = s2 / (float)NN - mean*mean;
        float sc = __ldg(&gamma[c]) * rsqrtf(var + 1e-5f);
        g_bnp[i*2] = sc;
        g_bnp[i*2 + 1] = __ldg(&beta[c]) - mean*sc;
    }
}

__global__ void k_bn_apply() {
    long i = blockIdx.x*(long)blockDim.x + threadIdx.x;
    if (i >= 4l*NE) return;
    int c = (int)(i & 127);
    int j = (int)(i / NE);
    float v = g_agg[i];
    float sc = __ldg(&g_bnp[(j*DD + c)*2]);
    float sh = __ldg(&g_bnp[(j*DD + c)*2 + 1]);
    float y = v*sc + sh;
    y = (y > 0.f) ? y : 0.01f*y;
    g_emb[i] += y;
}

// ---------------- relation embedding update: r = r @ Wrt^T + brt -----------
__global__ void k_rels_update(const float* __restrict__ Wrt, const float* __restrict__ brt,
                              const float* __restrict__ rin, float* __restrict__ rout) {
    __shared__ float rs[4*DD];
    int tid = threadIdx.x;
    if (tid < 4*DD) rs[tid] = rin[tid];
    __syncthreads();
    if (tid < 4*DD) {
        int j = tid >> 7, k = tid & 127;
        float acc = __ldg(&brt[k]);
        const float* wr = Wrt + k*DD;
#pragma unroll 4
        for (int m = 0; m < DD; m++) acc += rs[j*DD + m] * __ldg(&wr[m]);
        rout[tid] = acc;
    }
}

// ---------------- QKV GEMM: qkv[l] = stk[l] @ w_in^T + b_in ----------------
// stk[l] = finalEmb[map[l]], map = {3,0,2,1}. BM=32, lane: 4 rows x 12 cols.
__global__ __launch_bounds__(256) void k_qkv_gemm(
    const float* __restrict__ Wg, const float* __restrict__ bg)
{
    extern __shared__ float sm[];
    float* Wsm = sm;                 // [128][388] padded
    float* Xsm = sm + 128*388;       // 32*128
    int l = blockIdx.y;
    const int mp[4] = {3, 0, 2, 1};
    int m = mp[l];
    int r0 = blockIdx.x * 32;
    int tid = threadIdx.x;

    for (int e = tid; e < 384*128; e += 256) {
        int c = e >> 7, k = e & 127;
        Wsm[k*388 + c] = Wg[e];      // transpose: Wsm[k][c] = w_in[c][k]
    }
    for (int e = tid; e < 32*128; e += 256) {
        int r = e >> 7, k = e & 127;
        int gr = r0 + r;
        Xsm[e] = (gr < NN) ? g_agg[((size_t)m*NN + gr)*DD + k] : 0.0f;
    }
    __syncthreads();

    int wid = tid >> 5, lane = tid & 31;
    float acc[4][12];
#pragma unroll
    for (int r = 0; r < 4; r++)
#pragma unroll
        for (int c = 0; c < 12; c++) acc[r][c] = 0.f;
    const float* xb = Xsm + (wid*4)*128;
#pragma unroll 2
    for (int k = 0; k < 128; k++) {
        float4 w0 = *(const float4*)&Wsm[k*388 + lane*4];
        float4 w1 = *(const float4*)&Wsm[k*388 + 128 + lane*4];
        float4 w2 = *(const float4*)&Wsm[k*388 + 256 + lane*4];
#pragma unroll
        for (int r = 0; r < 4; r++) {
            float xv = xb[r*128 + k];
            acc[r][0] += xv*w0.x; acc[r][1] += xv*w0.y; acc[r][2]  += xv*w0.z; acc[r][3]  += xv*w0.w;
            acc[r][4] += xv*w1.x; acc[r][5] += xv*w1.y; acc[r][6]  += xv*w1.z; acc[r][7]  += xv*w1.w;
            acc[r][8] += xv*w2.x; acc[r][9] += xv*w2.y; acc[r][10] += xv*w2.z; acc[r][11] += xv*w2.w;
        }
    }
#pragma unroll
    for (int r = 0; r < 4; r++) {
        int gr = r0 + wid*4 + r;
        if (gr < NN) {
            float* op = g_qkv + ((size_t)l*NN + gr)*384;
#pragma unroll
            for (int p = 0; p < 3; p++) {
                float4 b4 = *(const float4*)&bg[p*128 + lane*4];
                float4 v = make_float4(acc[r][p*4+0] + b4.x, acc[r][p*4+1] + b4.y,
                                       acc[r][p*4+2] + b4.z, acc[r][p*4+3] + b4.w);
                *(float4*)&op[p*128 + lane*4] = v;
            }
        }
    }
}

// ---------------- tiny attention (L=4, 4 heads, hd=32) ---------------------
// one thread per (node, head, l): writes o into g_h[l][node][h*32..]
__global__ __launch_bounds__(256) void k_attn() {
    int t = blockIdx.x * blockDim.x + threadIdx.x;
    if (t >= NN*16) return;
    int node = t >> 4; int sub = t & 15; int h = sub >> 2; int l = sub & 3;
    const float scale = 0.17677669529663687f;   // 1/sqrt(32)
    size_t hb = (size_t)node*384 + h*32;

    const float* qp = g_qkv + (size_t)l*NN*384 + hb;
    float q[32];
#pragma unroll
    for (int i = 0; i < 8; i++) {
        float4 v = *(const float4*)&qp[i*4];
        q[i*4] = v.x*scale; q[i*4+1] = v.y*scale; q[i*4+2] = v.z*scale; q[i*4+3] = v.w*scale;
    }
    float s[4]; float mx = -1e30f;
#pragma unroll
    for (int m = 0; m < 4; m++) {
        const float* kp = g_qkv + (size_t)m*NN*384 + hb + 128;
        float a = 0.f;
#pragma unroll
        for (int i = 0; i < 8; i++) {
            float4 kv = *(const float4*)&kp[i*4];
            a += q[i*4]*kv.x + q[i*4+1]*kv.y + q[i*4+2]*kv.z + q[i*4+3]*kv.w;
        }
        s[m] = a; mx = fmaxf(mx, a);
    }
    float e[4]; float den = 0.f;
#pragma unroll
    for (int m = 0; m < 4; m++) { e[m] = expf(s[m] - mx); den += e[m]; }
    float inv = 1.0f/den;
    float o[32];
#pragma unroll
    for (int i = 0; i < 32; i++) o[i] = 0.f;
#pragma unroll
    for (int m = 0; m < 4; m++) {
        float a = e[m]*inv;
        const float* vp = g_qkv + (size_t)m*NN*384 + hb + 256;
#pragma unroll
        for (int i = 0; i < 8; i++) {
            float4 vv = *(const float4*)&vp[i*4];
            o[i*4] += a*vv.x; o[i*4+1] += a*vv.y; o[i*4+2] += a*vv.z; o[i*4+3] += a*vv.w;
        }
    }
    float* op = g_h + ((size_t)l*NN + node)*DD + h*32;
#pragma unroll
    for (int i = 0; i < 8; i++)
        *(float4*)&op[i*4] = make_float4(o[i*4], o[i*4+1], o[i*4+2], o[i*4+3]);
}

// ---------------- out-proj + alpha fusion: f = a*(o@Wout^T+b) + (1-a)*stk --
__global__ __launch_bounds__(256) void k_outproj(
    const float* __restrict__ Wg, const float* __restrict__ bg,
    const float* __restrict__ alphas)
{
    extern __shared__ float sm[];
    float* Wsm = sm;              // [128][132] padded
    float* Xsm = sm + 128*132;    // 64*128
    int l = blockIdx.y;
    const int mp[4] = {3, 0, 2, 1};
    int m = mp[l];
    int r0 = blockIdx.x * 64;
    int tid = threadIdx.x;

    for (int e = tid; e < 128*128; e += 256) {
        int c = e >> 7, k = e & 127;
        Wsm[k*132 + c] = Wg[e];   // Wsm[k][c] = w_out[c][k]
    }
    for (int e = tid; e < 64*128; e += 256) {
        int r = e >> 7, k = e & 127;
        int gr = r0 + r;
        Xsm[e] = (gr < NN) ? g_h[((size_t)l*NN + gr)*DD + k] : 0.0f;
    }
    __syncthreads();

    int wid = tid >> 5, lane = tid & 31;
    float acc[8][4];
#pragma unroll
    for (int r = 0; r < 8; r++) { acc[r][0]=0.f; acc[r][1]=0.f; acc[r][2]=0.f; acc[r][3]=0.f; }
    const float* xb = Xsm + (wid*8)*128;
#pragma unroll 4
    for (int k = 0; k < 128; k++) {
        float4 wv = *(const float4*)&Wsm[k*132 + lane*4];
#pragma unroll
        for (int r = 0; r < 8; r++) {
            float xv = xb[r*128 + k];
            acc[r][0] += xv*wv.x; acc[r][1] += xv*wv.y;
            acc[r][2] += xv*wv.z; acc[r][3] += xv*wv.w;
        }
    }
    float a = __ldg(&alphas[l]);
    float na = 1.0f - a;
    float4 b4 = *(const float4*)&bg[lane*4];
#pragma unroll
    for (int r = 0; r < 8; r++) {
        int gr = r0 + wid*8 + r;
        if (gr < NN) {
            float4 s4 = *(const float4*)&g_agg[((size_t)m*NN + gr)*DD + lane*4];
            float4 f4 = make_float4(a*(acc[r][0] + b4.x) + na*s4.x,
                                    a*(acc[r][1] + b4.y) + na*s4.y,
                                    a*(acc[r][2] + b4.z) + na*s4.z,
                                    a*(acc[r][3] + b4.w) + na*s4.w);
            *(float4*)&g_emb[((size_t)l*NN + gr)*DD + lane*4] = f4;
        }
    }
}

// ---------------- fusion score: sum_n sum_k leaky(f@Wf^T+bf)*q -------------
__global__ __launch_bounds__(256) void k_score(
    const float* __restrict__ Wg, const float* __restrict__ bg,
    const float* __restrict__ qv)
{
    extern __shared__ float sm[];
    float* Wsm = sm;              // [128][132]
    float* Xsm = sm + 128*132;    // 64*128
    __shared__ float wsum[8];
    int l = blockIdx.y;
    const int slotmap[4] = {0, 1, 3, 2};  // scores stacked (f0,f1,f3,f2)
    int r0 = blockIdx.x * 64;
    int tid = threadIdx.x;

    for (int e = tid; e < 128*128; e += 256) {
        int c = e >> 7, k = e & 127;
        Wsm[k*132 + c] = Wg[e];
    }
    for (int e = tid; e < 64*128; e += 256) {
        int r = e >> 7, k = e & 127;
        int gr = r0 + r;
        Xsm[e] = (gr < NN) ? g_emb[((size_t)l*NN + gr)*DD + k] : 0.0f;
    }
    __syncthreads();

    int wid = tid >> 5, lane = tid & 31;
    float acc[8][4];
#pragma unroll
    for (int r = 0; r < 8; r++) { acc[r][0]=0.f; acc[r][1]=0.f; acc[r][2]=0.f; acc[r][3]=0.f; }
    const float* xb = Xsm + (wid*8)*128;
#pragma unroll 4
    for (int k = 0; k < 128; k++) {
        float4 wv = *(const float4*)&Wsm[k*132 + lane*4];
#pragma unroll
        for (int r = 0; r < 8; r++) {
            float xv = xb[r*128 + k];
            acc[r][0] += xv*wv.x; acc[r][1] += xv*wv.y;
            acc[r][2] += xv*wv.z; acc[r][3] += xv*wv.w;
        }
    }
    float4 b4 = *(const float4*)&bg[lane*4];
    float4 q4 = *(const float4*)&qv[lane*4];
    float lsum = 0.f;
#pragma unroll
    for (int r = 0; r < 8; r++) {
        int gr = r0 + wid*8 + r;
        if (gr < NN) {
            float v0 = acc[r][0] + b4.x; v0 = (v0 > 0.f) ? v0 : 0.01f*v0;
            float v1 = acc[r][1] + b4.y; v1 = (v1 > 0.f) ? v1 : 0.01f*v1;
            float v2 = acc[r][2] + b4.z; v2 = (v2 > 0.f) ? v2 : 0.01f*v2;
            float v3 = acc[r][3] + b4.w; v3 = (v3 > 0.f) ? v3 : 0.01f*v3;
            lsum += v0*q4.x + v1*q4.y + v2*q4.z + v3*q4.w;
        }
    }
#pragma unroll
    for (int o = 16; o > 0; o >>= 1) lsum += __shfl_xor_sync(0xffffffffu, lsum, o);
    if (lane == 0) wsum[wid] = lsum;
    __syncthreads();
    if (tid == 0) {
        float tot = 0.f;
#pragma unroll
        for (int i = 0; i < 8; i++) tot += wsum[i];
        atomicAdd(&g_score[slotmap[l]], tot);
    }
}

__global__ void k_softmax_w() {
    if (threadIdx.x == 0 && blockIdx.x == 0) {
        float s[4]; float mx = -1e30f;
        for (int i = 0; i < 4; i++) { s[i] = g_score[i] / (float)NN; mx = fmaxf(mx, s[i]); }
        float e[4]; float den = 0.f;
        for (int i = 0; i < 4; i++) { e[i] = expf(s[i] - mx); den += e[i]; }
        for (int i = 0; i < 4; i++) g_w[i] = e[i] / den;
    }
}

// ---------------- final region + 5 outputs ---------------------------------
__global__ void k_final(float* __restrict__ out) {
    int i = blockIdx.x * blockDim.x + threadIdx.x;
    if (i >= NE) return;
    int c = i & 127;
    float f0 = g_emb[i], f1 = g_emb[NE + i], f2 = g_emb[2*NE + i], f3 = g_emb[3*NE + i];
    float w0 = __ldg(&g_w[0]), w1 = __ldg(&g_w[1]), w2 = __ldg(&g_w[2]), w3 = __ldg(&g_w[3]);
    // region = w0*n_f + w1*poi_f + w2*s_f + w3*d_f = w0*f0 + w1*f1 + w2*f3 + w3*f2
    float region = w0*f0 + w1*f1 + w2*f3 + w3*f2;
    const float* rf = g_rels[1];   // final rels after 3 ping-pong updates
    out[i]        = region;
    out[NE + i]   = region * __ldg(&rf[3*DD + c]);
    out[2*NE + i] = region * __ldg(&rf[0*DD + c]);
    out[3*NE + i] = region * __ldg(&rf[1*DD + c]);
    out[4*NE + i] = region * __ldg(&rf[2*DD + c]);
}

// ---------------- host launcher --------------------------------------------
extern "C" void kernel_launch(void* const* d_in, const int* in_sizes, int n_in,
                              void* d_out, int out_size) {
    const float* features   = (const float*)d_in[0];
    const float* rel_emb    = (const float*)d_in[1];
    const int*   edge_index = (const int*)  d_in[2];
    const float* W_gcn      = (const float*)d_in[3];
    const float* b_gcn      = (const float*)d_in[4];
    const float* bn_gamma   = (const float*)d_in[5];
    const float* bn_beta    = (const float*)d_in[6];
    const float* W_rt       = (const float*)d_in[7];
    const float* b_rt       = (const float*)d_in[8];
    const float* attn_w_in  = (const float*)d_in[9];
    const float* attn_b_in  = (const float*)d_in[10];
    const float* attn_w_out = (const float*)d_in[11];
    const float* attn_b_out = (const float*)d_in[12];
    const float* alphas     = (const float*)d_in[13];
    const float* fusion_q   = (const float*)d_in[14];
    const float* fusion_w   = (const float*)d_in[15];
    const float* fusion_b   = (const float*)d_in[16];
    float* out = (float*)d_out;

    const int GCN_SMEM  = (128*128 + 64*128) * 4;   // 96 KB
    const int QKV_SMEM  = (128*388 + 32*128) * 4;   // 210 KB
    const int T_SMEM    = (128*132 + 64*128) * 4;   // 98 KB
    cudaFuncSetAttribute(k_gcn_gemm, cudaFuncAttributeMaxDynamicSharedMemorySize, GCN_SMEM);
    cudaFuncSetAttribute(k_qkv_gemm, cudaFuncAttributeMaxDynamicSharedMemorySize, QKV_SMEM);
    cudaFuncSetAttribute(k_outproj,  cudaFuncAttributeMaxDynamicSharedMemorySize, T_SMEM);
    cudaFuncSetAttribute(k_score,    cudaFuncAttributeMaxDynamicSharedMemorySize, T_SMEM);

    // init
    k_init_emb<<<(NE + 255)/256, 256>>>(features);
    k_init_small<<<(4*NN + 255)/256, 256>>>(rel_emb);
    k_deg<<<(4*EE + 255)/256, 256>>>(edge_index);
    k_rsqrt_deg<<<(4*NN + 255)/256, 256>>>();

    dim3 ggrid((NN + 63)/64, 4);
    dim3 sgrid((EE + 7)/8, 4);
    dim3 bngrid(128, 4);
    int bnchunk = (NN + 127)/128;

    // rels ping-pong: layer0 reads buf0 -> writes buf1; layer1 buf1->buf0; layer2 buf0->buf1
    float* r0p; float* r1p;
    cudaGetSymbolAddress((void**)&r0p, g_rels);   // buf0
    r1p = r0p + 4*DD;                             // buf1

    const float* rin[3]  = { r0p, r1p, r0p };
    float*       rout[3] = { r1p, r0p, r1p };

    for (int i = 0; i < 2; i++) {
        k_gcn_gemm<<<ggrid, 256, GCN_SMEM>>>(W_gcn + i*DD*DD, b_gcn + i*DD, rin[i]);
        k_scatter<<<sgrid, 256>>>(edge_index);
        k_zero_stats<<<1, 1024>>>();
        k_bn_stats<<<bngrid, 128>>>(bnchunk);
        k_bn_finalize<<<1, 512>>>(bn_gamma + i*DD, bn_beta + i*DD);
        k_bn_apply<<<(4*NE + 255)/256, 256>>>();
        k_rels_update<<<1, 512>>>(W_rt + i*DD*DD, b_rt + i*DD, rin[i], rout[i]);
    }
    // final GCN layer (no BN/residual) -> result in g_agg
    k_gcn_gemm<<<ggrid, 256, GCN_SMEM>>>(W_gcn + 2*DD*DD, b_gcn + 2*DD, rin[2]);
    k_scatter<<<sgrid, 256>>>(edge_index);
    k_rels_update<<<1, 512>>>(W_rt + 2*DD*DD, b_rt + 2*DD, rin[2], rout[2]);

    // MHA + fusion
    dim3 qgrid((NN + 31)/32, 4);
    k_qkv_gemm<<<qgrid, 256, QKV_SMEM>>>(attn_w_in, attn_b_in);
    k_attn<<<(NN*16 + 255)/256, 256>>>();
    k_outproj<<<ggrid, 256, T_SMEM>>>(attn_w_out, attn_b_out, alphas);
    k_score<<<ggrid, 256, T_SMEM>>>(fusion_w, fusion_b, fusion_q);
    k_softmax_w<<<1, 32>>>();
    k_final<<<(NE + 255)/256, 256>>>(out);
}

// round 3
// speedup vs baseline: 1.2054x; 1.2054x over previous
#include <cuda_runtime.h>
#include <math.h>

#define NN 50000
#define DD 128
#define EE 400000
#define NE (NN*DD)

// ---------------- scratch (static device memory; no allocations) ----------
__device__ __align__(16) float g_emb[4*NE];      // embeddings; later reused as f-buffer
__device__ __align__(16) float g_h[4*NE];        // GEMM output h; later reused as attention o
__device__ __align__(16) float g_agg[4*NE];      // aggregation; final embeddings live here
__device__ __align__(16) float g_qkv[4ll*NN*384];
__device__ __align__(16) float g_dinv[4*NN];     // deg then rsqrt(deg)
__device__ __align__(16) float g_rels[2][4*DD];  // ping-pong relation embeddings
__device__ __align__(16) float g_stats[4*DD*2];  // BN sum/sumsq
__device__ __align__(16) float g_bnp[4*DD*2];    // BN scale/shift
__device__ float g_score[4];
__device__ float g_w[4];

// perm: processing order (n,poi,s,d) <- rel_emb/edge index (j+3)&3

// ---------------- init kernels --------------------------------------------
__global__ void k_init_emb(const float* __restrict__ feat) {
    int i = blockIdx.x * blockDim.x + threadIdx.x;
    if (i < NE) {
        float v = feat[i];
        g_emb[i] = v; g_emb[NE + i] = v; g_emb[2*NE + i] = v; g_emb[3*NE + i] = v;
    }
}

__global__ void k_init_small(const float* __restrict__ rel_emb) {
    int i = blockIdx.x * blockDim.x + threadIdx.x;
    if (i < 4*NN) g_dinv[i] = 1.0f;           // deg starts at 1 (self loop)
    if (i < 4*DD) {
        int j = i >> 7, c = i & 127;
        int p = (j + 3) & 3;
        g_rels[0][i] = rel_emb[p*DD + c];
    }
    if (i < 4) g_score[i] = 0.0f;
}

__global__ void k_deg(const int* __restrict__ ei) {
    int t = blockIdx.x * blockDim.x + threadIdx.x;
    if (t >= 4*EE) return;
    int j = t / EE; int e = t - j*EE;
    int p = (j + 3) & 3;
    int dst = ei[(size_t)p*2*EE + EE + e];
    atomicAdd(&g_dinv[j*NN + dst], 1.0f);
}

__global__ void k_rsqrt_deg() {
    int i = blockIdx.x * blockDim.x + threadIdx.x;
    if (i < 4*NN) g_dinv[i] = rsqrtf(g_dinv[i]);
}

// ---------------- GCN GEMM: h = (emb*rels) @ W ; agg = h*dinv^2 + b --------
// block 256 = 8 warps; BM=64 rows; each warp 8 rows, each lane 4 cols.
__global__ __launch_bounds__(256) void k_gcn_gemm(
    const float* __restrict__ Wg, const float* __restrict__ bg,
    const float* __restrict__ rels)
{
    extern __shared__ float sm[];
    float* Wsm = sm;               // 128*128
    float* Xsm = sm + 128*128;     // 64*128
    int j = blockIdx.y;
    int r0 = blockIdx.x * 64;
    int tid = threadIdx.x;

    for (int e = tid; e < 128*128; e += 256) Wsm[e] = Wg[e];
    const float* rrow = rels + j*DD;
    for (int e = tid; e < 64*128; e += 256) {
        int r = e >> 7, k = e & 127;
        int gr = r0 + r;
        Xsm[e] = (gr < NN) ? g_emb[((size_t)j*NN + gr)*DD + k] * __ldg(&rrow[k]) : 0.0f;
    }
    __syncthreads();

    int wid = tid >> 5, lane = tid & 31;
    float acc[8][4];
#pragma unroll
    for (int r = 0; r < 8; r++) { acc[r][0]=0.f; acc[r][1]=0.f; acc[r][2]=0.f; acc[r][3]=0.f; }
    const float* xb = Xsm + (wid*8)*128;
#pragma unroll 4
    for (int k = 0; k < 128; k++) {
        float4 wv = *(const float4*)&Wsm[k*128 + lane*4];
#pragma unroll
        for (int r = 0; r < 8; r++) {
            float xv = xb[r*128 + k];
            acc[r][0] += xv*wv.x; acc[r][1] += xv*wv.y;
            acc[r][2] += xv*wv.z; acc[r][3] += xv*wv.w;
        }
    }
    float4 b4 = *(const float4*)&bg[lane*4];
#pragma unroll
    for (int r = 0; r < 8; r++) {
        int gr = r0 + wid*8 + r;
        if (gr < NN) {
            size_t off = ((size_t)j*NN + gr)*DD + lane*4;
            float4 h4 = make_float4(acc[r][0], acc[r][1], acc[r][2], acc[r][3]);
            *(float4*)&g_h[off] = h4;
            float di = __ldg(&g_dinv[j*NN + gr]); float d2 = di*di;
            float4 a4 = make_float4(h4.x*d2 + b4.x, h4.y*d2 + b4.y,
                                    h4.z*d2 + b4.z, h4.w*d2 + b4.w);
            *(float4*)&g_agg[off] = a4;
        }
    }
}

// ---------------- edge scatter: agg[dst] += h[src]*norm --------------------
// one warp per edge; each lane reduces a 16B chunk with a single vector RED.
__global__ __launch_bounds__(256) void k_scatter(const int* __restrict__ ei) {
    int j = blockIdx.y;
    int wid = threadIdx.x >> 5, lane = threadIdx.x & 31;
    long e = (long)blockIdx.x*8 + wid;
    if (e >= EE) return;
    int p = (j + 3) & 3;
    const int* base = ei + (size_t)p*2*EE;
    int src = __ldg(&base[e]);
    int dst = __ldg(&base[EE + e]);
    float norm = __ldg(&g_dinv[j*NN + src]) * __ldg(&g_dinv[j*NN + dst]);
    float4 h4 = *(const float4*)&g_h[((size_t)j*NN + src)*DD + lane*4];
    float* ap = &g_agg[((size_t)j*NN + dst)*DD + lane*4];
    asm volatile("red.global.add.v4.f32 [%0], {%1, %2, %3, %4};"
                 :: "l"(ap), "f"(h4.x*norm), "f"(h4.y*norm),
                    "f"(h4.z*norm), "f"(h4.w*norm)
                 : "memory");
}

// ---------------- BatchNorm ------------------------------------------------
__global__ void k_zero_stats() { int i = threadIdx.x; if (i < 4*DD*2) g_stats[i] = 0.f; }

__global__ void k_bn_stats(int chunk) {
    int j = blockIdx.y, c = threadIdx.x;
    int rs = blockIdx.x * chunk;
    int re = min(rs + chunk, NN);
    float s = 0.f, s2 = 0.f;
    const float* base = g_agg + (size_t)j*NE;
    for (int r = rs; r < re; r++) {
        float v = base[(size_t)r*DD + c];
        s += v; s2 += v*v;
    }
    atomicAdd(&g_stats[(j*DD + c)*2], s);
    atomicAdd(&g_stats[(j*DD + c)*2 + 1], s2);
}

__global__ void k_bn_finalize(const float* __restrict__ gamma, const float* __restrict__ beta) {
    int i = threadIdx.x;
    if (i < 4*DD) {
        int c = i & 127;
        float s = g_stats[i*2], s2 = g_stats[i*2 + 1];
        float mean = s / (float)NN;
        float var = s2 / (float)NN - mean*mean;
        float sc = __ldg(&gamma[c]) * rsqrtf(var + 1e-5f);
        g_bnp[i*2] = sc;
        g_bnp[i*2 + 1] = __ldg(&beta[c]) - mean*sc;
    }
}

__global__ void k_bn_apply() {
    long i = blockIdx.x*(long)blockDim.x + threadIdx.x;
    if (i >= 4l*NE) return;
    int c = (int)(i & 127);
    int j = (int)(i / NE);
    float v = g_agg[i];
    float sc = __ldg(&g_bnp[(j*DD + c)*2]);
    float sh = __ldg(&g_bnp[(j*DD + c)*2 + 1]);
    float y = v*sc + sh;
    y = (y > 0.f) ? y : 0.01f*y;
    g_emb[i] += y;
}

// ---------------- relation embedding update: r = r @ Wrt^T + brt -----------
__global__ void k_rels_update(const float* __restrict__ Wrt, const float* __restrict__ brt,
                              const float* __restrict__ rin, float* __restrict__ rout) {
    __shared__ float rs[4*DD];
    int tid = threadIdx.x;
    if (tid < 4*DD) rs[tid] = rin[tid];
    __syncthreads();
    if (tid < 4*DD) {
        int j = tid >> 7, k = tid & 127;
        float acc = __ldg(&brt[k]);
        const float* wr = Wrt + k*DD;
#pragma unroll 4
        for (int m = 0; m < DD; m++) acc += rs[j*DD + m] * __ldg(&wr[m]);
        rout[tid] = acc;
    }
}

// ---------------- QKV GEMM: qkv[l] = stk[l] @ w_in^T + b_in ----------------
// stk[l] = finalEmb[map[l]], map = {3,0,2,1}. BM=32, lane: 4 rows x 12 cols.
__global__ __launch_bounds__(256) void k_qkv_gemm(
    const float* __restrict__ Wg, const float* __restrict__ bg)
{
    extern __shared__ float sm[];
    float* Wsm = sm;                 // [128][388] padded
    float* Xsm = sm + 128*388;       // 32*128
    int l = blockIdx.y;
    const int mp[4] = {3, 0, 2, 1};
    int m = mp[l];
    int r0 = blockIdx.x * 32;
    int tid = threadIdx.x;

    for (int e = tid; e < 384*128; e += 256) {
        int c = e >> 7, k = e & 127;
        Wsm[k*388 + c] = Wg[e];      // transpose: Wsm[k][c] = w_in[c][k]
    }
    for (int e = tid; e < 32*128; e += 256) {
        int r = e >> 7, k = e & 127;
        int gr = r0 + r;
        Xsm[e] = (gr < NN) ? g_agg[((size_t)m*NN + gr)*DD + k] : 0.0f;
    }
    __syncthreads();

    int wid = tid >> 5, lane = tid & 31;
    float acc[4][12];
#pragma unroll
    for (int r = 0; r < 4; r++)
#pragma unroll
        for (int c = 0; c < 12; c++) acc[r][c] = 0.f;
    const float* xb = Xsm + (wid*4)*128;
#pragma unroll 2
    for (int k = 0; k < 128; k++) {
        float4 w0 = *(const float4*)&Wsm[k*388 + lane*4];
        float4 w1 = *(const float4*)&Wsm[k*388 + 128 + lane*4];
        float4 w2 = *(const float4*)&Wsm[k*388 + 256 + lane*4];
#pragma unroll
        for (int r = 0; r < 4; r++) {
            float xv = xb[r*128 + k];
            acc[r][0] += xv*w0.x; acc[r][1] += xv*w0.y; acc[r][2]  += xv*w0.z; acc[r][3]  += xv*w0.w;
            acc[r][4] += xv*w1.x; acc[r][5] += xv*w1.y; acc[r][6]  += xv*w1.z; acc[r][7]  += xv*w1.w;
            acc[r][8] += xv*w2.x; acc[r][9] += xv*w2.y; acc[r][10] += xv*w2.z; acc[r][11] += xv*w2.w;
        }
    }
#pragma unroll
    for (int r = 0; r < 4; r++) {
        int gr = r0 + wid*4 + r;
        if (gr < NN) {
            float* op = g_qkv + ((size_t)l*NN + gr)*384;
#pragma unroll
            for (int p = 0; p < 3; p++) {
                float4 b4 = *(const float4*)&bg[p*128 + lane*4];
                float4 v = make_float4(acc[r][p*4+0] + b4.x, acc[r][p*4+1] + b4.y,
                                       acc[r][p*4+2] + b4.z, acc[r][p*4+3] + b4.w);
                *(float4*)&op[p*128 + lane*4] = v;
            }
        }
    }
}

// ---------------- tiny attention (L=4, 4 heads, hd=32) ---------------------
// one thread per (node, head, l): writes o into g_h[l][node][h*32..]
__global__ __launch_bounds__(256) void k_attn() {
    int t = blockIdx.x * blockDim.x + threadIdx.x;
    if (t >= NN*16) return;
    int node = t >> 4; int sub = t & 15; int h = sub >> 2; int l = sub & 3;
    const float scale = 0.17677669529663687f;   // 1/sqrt(32)
    size_t hb = (size_t)node*384 + h*32;

    const float* qp = g_qkv + (size_t)l*NN*384 + hb;
    float q[32];
#pragma unroll
    for (int i = 0; i < 8; i++) {
        float4 v = *(const float4*)&qp[i*4];
        q[i*4] = v.x*scale; q[i*4+1] = v.y*scale; q[i*4+2] = v.z*scale; q[i*4+3] = v.w*scale;
    }
    float s[4]; float mx = -1e30f;
#pragma unroll
    for (int m = 0; m < 4; m++) {
        const float* kp = g_qkv + (size_t)m*NN*384 + hb + 128;
        float a = 0.f;
#pragma unroll
        for (int i = 0; i < 8; i++) {
            float4 kv = *(const float4*)&kp[i*4];
            a += q[i*4]*kv.x + q[i*4+1]*kv.y + q[i*4+2]*kv.z + q[i*4+3]*kv.w;
        }
        s[m] = a; mx = fmaxf(mx, a);
    }
    float e[4]; float den = 0.f;
#pragma unroll
    for (int m = 0; m < 4; m++) { e[m] = expf(s[m] - mx); den += e[m]; }
    float inv = 1.0f/den;
    float o[32];
#pragma unroll
    for (int i = 0; i < 32; i++) o[i] = 0.f;
#pragma unroll
    for (int m = 0; m < 4; m++) {
        float a = e[m]*inv;
        const float* vp = g_qkv + (size_t)m*NN*384 + hb + 256;
#pragma unroll
        for (int i = 0; i < 8; i++) {
            float4 vv = *(const float4*)&vp[i*4];
            o[i*4] += a*vv.x; o[i*4+1] += a*vv.y; o[i*4+2] += a*vv.z; o[i*4+3] += a*vv.w;
        }
    }
    float* op = g_h + ((size_t)l*NN + node)*DD + h*32;
#pragma unroll
    for (int i = 0; i < 8; i++)
        *(float4*)&op[i*4] = make_float4(o[i*4], o[i*4+1], o[i*4+2], o[i*4+3]);
}

// ---------------- out-proj + alpha fusion: f = a*(o@Wout^T+b) + (1-a)*stk --
__global__ __launch_bounds__(256) void k_outproj(
    const float* __restrict__ Wg, const float* __restrict__ bg,
    const float* __restrict__ alphas)
{
    extern __shared__ float sm[];
    float* Wsm = sm;              // [128][132] padded
    float* Xsm = sm + 128*132;    // 64*128
    int l = blockIdx.y;
    const int mp[4] = {3, 0, 2, 1};
    int m = mp[l];
    int r0 = blockIdx.x * 64;
    int tid = threadIdx.x;

    for (int e = tid; e < 128*128; e += 256) {
        int c = e >> 7, k = e & 127;
        Wsm[k*132 + c] = Wg[e];   // Wsm[k][c] = w_out[c][k]
    }
    for (int e = tid; e < 64*128; e += 256) {
        int r = e >> 7, k = e & 127;
        int gr = r0 + r;
        Xsm[e] = (gr < NN) ? g_h[((size_t)l*NN + gr)*DD + k] : 0.0f;
    }
    __syncthreads();

    int wid = tid >> 5, lane = tid & 31;
    float acc[8][4];
#pragma unroll
    for (int r = 0; r < 8; r++) { acc[r][0]=0.f; acc[r][1]=0.f; acc[r][2]=0.f; acc[r][3]=0.f; }
    const float* xb = Xsm + (wid*8)*128;
#pragma unroll 4
    for (int k = 0; k < 128; k++) {
        float4 wv = *(const float4*)&Wsm[k*132 + lane*4];
#pragma unroll
        for (int r = 0; r < 8; r++) {
            float xv = xb[r*128 + k];
            acc[r][0] += xv*wv.x; acc[r][1] += xv*wv.y;
            acc[r][2] += xv*wv.z; acc[r][3] += xv*wv.w;
        }
    }
    float a = __ldg(&alphas[l]);
    float na = 1.0f - a;
    float4 b4 = *(const float4*)&bg[lane*4];
#pragma unroll
    for (int r = 0; r < 8; r++) {
        int gr = r0 + wid*8 + r;
        if (gr < NN) {
            float4 s4 = *(const float4*)&g_agg[((size_t)m*NN + gr)*DD + lane*4];
            float4 f4 = make_float4(a*(acc[r][0] + b4.x) + na*s4.x,
                                    a*(acc[r][1] + b4.y) + na*s4.y,
                                    a*(acc[r][2] + b4.z) + na*s4.z,
                                    a*(acc[r][3] + b4.w) + na*s4.w);
            *(float4*)&g_emb[((size_t)l*NN + gr)*DD + lane*4] = f4;
        }
    }
}

// ---------------- fusion score: sum_n sum_k leaky(f@Wf^T+bf)*q -------------
__global__ __launch_bounds__(256) void k_score(
    const float* __restrict__ Wg, const float* __restrict__ bg,
    const float* __restrict__ qv)
{
    extern __shared__ float sm[];
    float* Wsm = sm;              // [128][132]
    float* Xsm = sm + 128*132;    // 64*128
    __shared__ float wsum[8];
    int l = blockIdx.y;
    const int slotmap[4] = {0, 1, 3, 2};  // scores stacked (f0,f1,f3,f2)
    int r0 = blockIdx.x * 64;
    int tid = threadIdx.x;

    for (int e = tid; e < 128*128; e += 256) {
        int c = e >> 7, k = e & 127;
        Wsm[k*132 + c] = Wg[e];
    }
    for (int e = tid; e < 64*128; e += 256) {
        int r = e >> 7, k = e & 127;
        int gr = r0 + r;
        Xsm[e] = (gr < NN) ? g_emb[((size_t)l*NN + gr)*DD + k] : 0.0f;
    }
    __syncthreads();

    int wid = tid >> 5, lane = tid & 31;
    float acc[8][4];
#pragma unroll
    for (int r = 0; r < 8; r++) { acc[r][0]=0.f; acc[r][1]=0.f; acc[r][2]=0.f; acc[r][3]=0.f; }
    const float* xb = Xsm + (wid*8)*128;
#pragma unroll 4
    for (int k = 0; k < 128; k++) {
        float4 wv = *(const float4*)&Wsm[k*132 + lane*4];
#pragma unroll
        for (int r = 0; r < 8; r++) {
            float xv = xb[r*128 + k];
            acc[r][0] += xv*wv.x; acc[r][1] += xv*wv.y;
            acc[r][2] += xv*wv.z; acc[r][3] += xv*wv.w;
        }
    }
    float4 b4 = *(const float4*)&bg[lane*4];
    float4 q4 = *(const float4*)&qv[lane*4];
    float lsum = 0.f;
#pragma unroll
    for (int r = 0; r < 8; r++) {
        int gr = r0 + wid*8 + r;
        if (gr < NN) {
            float v0 = acc[r][0] + b4.x; v0 = (v0 > 0.f) ? v0 : 0.01f*v0;
            float v1 = acc[r][1] + b4.y; v1 = (v1 > 0.f) ? v1 : 0.01f*v1;
            float v2 = acc[r][2] + b4.z; v2 = (v2 > 0.f) ? v2 : 0.01f*v2;
            float v3 = acc[r][3] + b4.w; v3 = (v3 > 0.f) ? v3 : 0.01f*v3;
            lsum += v0*q4.x + v1*q4.y + v2*q4.z + v3*q4.w;
        }
    }
#pragma unroll
    for (int o = 16; o > 0; o >>= 1) lsum += __shfl_xor_sync(0xffffffffu, lsum, o);
    if (lane == 0) wsum[wid] = lsum;
    __syncthreads();
    if (tid == 0) {
        float tot = 0.f;
#pragma unroll
        for (int i = 0; i < 8; i++) tot += wsum[i];
        atomicAdd(&g_score[slotmap[l]], tot);
    }
}

__global__ void k_softmax_w() {
    if (threadIdx.x == 0 && blockIdx.x == 0) {
        float s[4]; float mx = -1e30f;
        for (int i = 0; i < 4; i++) { s[i] = g_score[i] / (float)NN; mx = fmaxf(mx, s[i]); }
        float e[4]; float den = 0.f;
        for (int i = 0; i < 4; i++) { e[i] = expf(s[i] - mx); den += e[i]; }
        for (int i = 0; i < 4; i++) g_w[i] = e[i] / den;
    }
}

// ---------------- final region + 5 outputs ---------------------------------
__global__ void k_final(float* __restrict__ out) {
    int i = blockIdx.x * blockDim.x + threadIdx.x;
    if (i >= NE) return;
    int c = i & 127;
    float f0 = g_emb[i], f1 = g_emb[NE + i], f2 = g_emb[2*NE + i], f3 = g_emb[3*NE + i];
    float w0 = __ldg(&g_w[0]), w1 = __ldg(&g_w[1]), w2 = __ldg(&g_w[2]), w3 = __ldg(&g_w[3]);
    // region = w0*n_f + w1*poi_f + w2*s_f + w3*d_f = w0*f0 + w1*f1 + w2*f3 + w3*f2
    float region = w0*f0 + w1*f1 + w2*f3 + w3*f2;
    const float* rf = g_rels[1];   // final rels after 3 ping-pong updates
    out[i]        = region;
    out[NE + i]   = region * __ldg(&rf[3*DD + c]);
    out[2*NE + i] = region * __ldg(&rf[0*DD + c]);
    out[3*NE + i] = region * __ldg(&rf[1*DD + c]);
    out[4*NE + i] = region * __ldg(&rf[2*DD + c]);
}

// ---------------- host launcher --------------------------------------------
extern "C" void kernel_launch(void* const* d_in, const int* in_sizes, int n_in,
                              void* d_out, int out_size) {
    const float* features   = (const float*)d_in[0];
    const float* rel_emb    = (const float*)d_in[1];
    const int*   edge_index = (const int*)  d_in[2];
    const float* W_gcn      = (const float*)d_in[3];
    const float* b_gcn      = (const float*)d_in[4];
    const float* bn_gamma   = (const float*)d_in[5];
    const float* bn_beta    = (const float*)d_in[6];
    const float* W_rt       = (const float*)d_in[7];
    const float* b_rt       = (const float*)d_in[8];
    const float* attn_w_in  = (const float*)d_in[9];
    const float* attn_b_in  = (const float*)d_in[10];
    const float* attn_w_out = (const float*)d_in[11];
    const float* attn_b_out = (const float*)d_in[12];
    const float* alphas     = (const float*)d_in[13];
    const float* fusion_q   = (const float*)d_in[14];
    const float* fusion_w   = (const float*)d_in[15];
    const float* fusion_b   = (const float*)d_in[16];
    float* out = (float*)d_out;

    const int GCN_SMEM  = (128*128 + 64*128) * 4;   // 96 KB
    const int QKV_SMEM  = (128*388 + 32*128) * 4;   // 210 KB
    const int T_SMEM    = (128*132 + 64*128) * 4;   // 98 KB
    cudaFuncSetAttribute(k_gcn_gemm, cudaFuncAttributeMaxDynamicSharedMemorySize, GCN_SMEM);
    cudaFuncSetAttribute(k_qkv_gemm, cudaFuncAttributeMaxDynamicSharedMemorySize, QKV_SMEM);
    cudaFuncSetAttribute(k_outproj,  cudaFuncAttributeMaxDynamicSharedMemorySize, T_SMEM);
    cudaFuncSetAttribute(k_score,    cudaFuncAttributeMaxDynamicSharedMemorySize, T_SMEM);

    // init
    k_init_emb<<<(NE + 255)/256, 256>>>(features);
    k_init_small<<<(4*NN + 255)/256, 256>>>(rel_emb);
    k_deg<<<(4*EE + 255)/256, 256>>>(edge_index);
    k_rsqrt_deg<<<(4*NN + 255)/256, 256>>>();

    dim3 ggrid((NN + 63)/64, 4);
    dim3 sgrid((EE + 7)/8, 4);
    dim3 bngrid(128, 4);
    int bnchunk = (NN + 127)/128;

    // rels ping-pong: layer0 reads buf0 -> writes buf1; layer1 buf1->buf0; layer2 buf0->buf1
    float* r0p; float* r1p;
    cudaGetSymbolAddress((void**)&r0p, g_rels);   // buf0
    r1p = r0p + 4*DD;                             // buf1

    const float* rin[3]  = { r0p, r1p, r0p };
    float*       rout[3] = { r1p, r0p, r1p };

    for (int i = 0; i < 2; i++) {
        k_gcn_gemm<<<ggrid, 256, GCN_SMEM>>>(W_gcn + i*DD*DD, b_gcn + i*DD, rin[i]);
        k_scatter<<<sgrid, 256>>>(edge_index);
        k_zero_stats<<<1, 1024>>>();
        k_bn_stats<<<bngrid, 128>>>(bnchunk);
        k_bn_finalize<<<1, 512>>>(bn_gamma + i*DD, bn_beta + i*DD);
        k_bn_apply<<<(4*NE + 255)/256, 256>>>();
        k_rels_update<<<1, 512>>>(W_rt + i*DD*DD, b_rt + i*DD, rin[i], rout[i]);
    }
    // final GCN layer (no BN/residual) -> result in g_agg
    k_gcn_gemm<<<ggrid, 256, GCN_SMEM>>>(W_gcn + 2*DD*DD, b_gcn + 2*DD, rin[2]);
    k_scatter<<<sgrid, 256>>>(edge_index);
    k_rels_update<<<1, 512>>>(W_rt + 2*DD*DD, b_rt + 2*DD, rin[2], rout[2]);

    // MHA + fusion
    dim3 qgrid((NN + 31)/32, 4);
    k_qkv_gemm<<<qgrid, 256, QKV_SMEM>>>(attn_w_in, attn_b_in);
    k_attn<<<(NN*16 + 255)/256, 256>>>();
    k_outproj<<<ggrid, 256, T_SMEM>>>(attn_w_out, attn_b_out, alphas);
    k_score<<<ggrid, 256, T_SMEM>>>(fusion_w, fusion_b, fusion_q);
    k_softmax_w<<<1, 32>>>();
    k_final<<<(NE + 255)/256, 256>>>(out);
}

// round 4
// speedup vs baseline: 1.3303x; 1.1036x over previous
#include <cuda_runtime.h>
#include <math.h>

#define NN 50000
#define DD 128
#define EE 400000
#define NE (NN*DD)
#define NB4 (4*NN)
#define SCAN_BLOCKS ((NB4 + 1023)/1024)

// ---------------- scratch (static device memory; no allocations) ----------
__device__ __align__(16) float g_emb[4*NE];      // embeddings; later reused as f-buffer
__device__ __align__(16) float g_h[4*NE];        // GEMM output h; later reused as attention o
__device__ __align__(16) float g_agg[4*NE];      // aggregation; final embeddings live here
__device__ __align__(16) float g_qkv[4ll*NN*384];
__device__ __align__(16) float g_dinv[NB4];      // rsqrt(deg)
__device__ __align__(16) int   g_cnt[NB4];       // per-(rel,dst) edge count
__device__ __align__(16) int   g_off[NB4];       // CSR offsets (exclusive scan of cnt)
__device__ __align__(16) int   g_cur[NB4];       // placement cursors
__device__ __align__(16) int   g_bsum[SCAN_BLOCKS];
__device__ __align__(16) int   g_esrc[4*EE];     // src ids bucketed by (rel,dst)
__device__ __align__(16) float g_rels[2][4*DD];  // ping-pong relation embeddings
__device__ __align__(16) float g_stats[4*DD*2];  // BN sum/sumsq
__device__ __align__(16) float g_bnp[4*DD*2];    // BN scale/shift
__device__ float g_score[4];
__device__ float g_w[4];

// perm: processing order (n,poi,s,d) <- rel_emb/edge index (j+3)&3

// ---------------- init kernels --------------------------------------------
__global__ void k_init_emb(const float* __restrict__ feat) {
    int i = blockIdx.x * blockDim.x + threadIdx.x;
    if (i < NE) {
        float v = feat[i];
        g_emb[i] = v; g_emb[NE + i] = v; g_emb[2*NE + i] = v; g_emb[3*NE + i] = v;
    }
}

__global__ void k_init_small(const float* __restrict__ rel_emb) {
    int i = blockIdx.x * blockDim.x + threadIdx.x;
    if (i < NB4) g_cnt[i] = 0;
    if (i < 4*DD) {
        int j = i >> 7, c = i & 127;
        int p = (j + 3) & 3;
        g_rels[0][i] = rel_emb[p*DD + c];
    }
    if (i < 4) g_score[i] = 0.0f;
}

// ---------------- CSR build: histogram -> scan -> reorder ------------------
__global__ void k_hist(const int* __restrict__ ei) {
    int t = blockIdx.x * blockDim.x + threadIdx.x;
    if (t >= 4*EE) return;
    int j = t / EE; int e = t - j*EE;
    int p = (j + 3) & 3;
    int dst = ei[(size_t)p*2*EE + EE + e];
    atomicAdd(&g_cnt[j*NN + dst], 1);
}

__global__ __launch_bounds__(1024) void k_scan1() {
    __shared__ int s[1024];
    int i = blockIdx.x * 1024 + threadIdx.x;
    int v = (i < NB4) ? g_cnt[i] : 0;
    s[threadIdx.x] = v;
    __syncthreads();
    for (int o = 1; o < 1024; o <<= 1) {
        int t = (threadIdx.x >= o) ? s[threadIdx.x - o] : 0;
        __syncthreads();
        s[threadIdx.x] += t;
        __syncthreads();
    }
    if (i < NB4) g_off[i] = s[threadIdx.x] - v;   // exclusive
    if (threadIdx.x == 1023) g_bsum[blockIdx.x] = s[1023];
}

__global__ void k_scan2() {
    if (threadIdx.x == 0) {
        int acc = 0;
        for (int b = 0; b < SCAN_BLOCKS; b++) { int v = g_bsum[b]; g_bsum[b] = acc; acc += v; }
    }
}

__global__ void k_scan3() {
    int i = blockIdx.x * blockDim.x + threadIdx.x;
    if (i < NB4) {
        int o = g_off[i] + g_bsum[i >> 10];
        g_off[i] = o; g_cur[i] = o;
        g_dinv[i] = rsqrtf((float)g_cnt[i] + 1.0f);
    }
}

__global__ void k_reorder(const int* __restrict__ ei) {
    int t = blockIdx.x * blockDim.x + threadIdx.x;
    if (t >= 4*EE) return;
    int j = t / EE; int e = t - j*EE;
    int p = (j + 3) & 3;
    const int* base = ei + (size_t)p*2*EE;
    int src = __ldg(&base[e]);
    int dst = __ldg(&base[EE + e]);
    int pos = atomicAdd(&g_cur[j*NN + dst], 1);
    g_esrc[pos] = src;
}

// ---------------- GCN GEMM: h = (emb*rels) @ W -----------------------------
// block 256 = 8 warps; BM=64 rows; each warp 8 rows, each lane 4 cols.
__global__ __launch_bounds__(256) void k_gcn_gemm(
    const float* __restrict__ Wg, const float* __restrict__ rels)
{
    extern __shared__ float sm[];
    float* Wsm = sm;               // 128*128
    float* Xsm = sm + 128*128;     // 64*128
    int j = blockIdx.y;
    int r0 = blockIdx.x * 64;
    int tid = threadIdx.x;

    for (int e = tid; e < 128*128; e += 256) Wsm[e] = Wg[e];
    const float* rrow = rels + j*DD;
    for (int e = tid; e < 64*128; e += 256) {
        int r = e >> 7, k = e & 127;
        int gr = r0 + r;
        Xsm[e] = (gr < NN) ? g_emb[((size_t)j*NN + gr)*DD + k] * __ldg(&rrow[k]) : 0.0f;
    }
    __syncthreads();

    int wid = tid >> 5, lane = tid & 31;
    float acc[8][4];
#pragma unroll
    for (int r = 0; r < 8; r++) { acc[r][0]=0.f; acc[r][1]=0.f; acc[r][2]=0.f; acc[r][3]=0.f; }
    const float* xb = Xsm + (wid*8)*128;
#pragma unroll 4
    for (int k = 0; k < 128; k++) {
        float4 wv = *(const float4*)&Wsm[k*128 + lane*4];
#pragma unroll
        for (int r = 0; r < 8; r++) {
            float xv = xb[r*128 + k];
            acc[r][0] += xv*wv.x; acc[r][1] += xv*wv.y;
            acc[r][2] += xv*wv.z; acc[r][3] += xv*wv.w;
        }
    }
#pragma unroll
    for (int r = 0; r < 8; r++) {
        int gr = r0 + wid*8 + r;
        if (gr < NN) {
            size_t off = ((size_t)j*NN + gr)*DD + lane*4;
            *(float4*)&g_h[off] = make_float4(acc[r][0], acc[r][1], acc[r][2], acc[r][3]);
        }
    }
}

// ---------------- gather: agg = b + h[dst]*d2 + sum h[src]*dinv_s*dinv_d ---
// one warp per (rel, dst); each lane owns a 16B column chunk.
__global__ __launch_bounds__(256) void k_gather(const float* __restrict__ bg) {
    int j = blockIdx.y;
    int wid = threadIdx.x >> 5, lane = threadIdx.x & 31;
    int dst = blockIdx.x*8 + wid;
    if (dst >= NN) return;
    int idx = j*NN + dst;
    int beg = __ldg(&g_off[idx]);
    int cnt = __ldg(&g_cnt[idx]);
    float dd = __ldg(&g_dinv[idx]);
    float d2 = dd*dd;

    float4 b4 = *(const float4*)&bg[lane*4];
    float4 hd = *(const float4*)&g_h[((size_t)idx)*DD + lane*4];
    float ax = b4.x + hd.x*d2, ay = b4.y + hd.y*d2;
    float az = b4.z + hd.z*d2, aw = b4.w + hd.w*d2;

    int src_nx = (cnt > 0) ? __ldg(&g_esrc[beg]) : 0;
    for (int t = 0; t < cnt; t++) {
        int src = src_nx;
        src_nx = (t + 1 < cnt) ? __ldg(&g_esrc[beg + t + 1]) : 0;
        float nm = __ldg(&g_dinv[j*NN + src]) * dd;
        float4 hs = *(const float4*)&g_h[((size_t)j*NN + src)*DD + lane*4];
        ax += hs.x*nm; ay += hs.y*nm; az += hs.z*nm; aw += hs.w*nm;
    }
    *(float4*)&g_agg[((size_t)idx)*DD + lane*4] = make_float4(ax, ay, az, aw);
}

// ---------------- BatchNorm ------------------------------------------------
__global__ void k_zero_stats() { int i = threadIdx.x; if (i < 4*DD*2) g_stats[i] = 0.f; }

__global__ void k_bn_stats(int chunk) {
    int j = blockIdx.y, c = threadIdx.x;
    int rs = blockIdx.x * chunk;
    int re = min(rs + chunk, NN);
    float s = 0.f, s2 = 0.f;
    const float* base = g_agg + (size_t)j*NE;
    for (int r = rs; r < re; r++) {
        float v = base[(size_t)r*DD + c];
        s += v; s2 += v*v;
    }
    atomicAdd(&g_stats[(j*DD + c)*2], s);
    atomicAdd(&g_stats[(j*DD + c)*2 + 1], s2);
}

__global__ void k_bn_finalize(const float* __restrict__ gamma, const float* __restrict__ beta) {
    int i = threadIdx.x;
    if (i < 4*DD) {
        int c = i & 127;
        float s = g_stats[i*2], s2 = g_stats[i*2 + 1];
        float mean = s / (float)NN;
        float var = s2 / (float)NN - mean*mean;
        float sc = __ldg(&gamma[c]) * rsqrtf(var + 1e-5f);
        g_bnp[i*2] = sc;
        g_bnp[i*2 + 1] = __ldg(&beta[c]) - mean*sc;
    }
}

__global__ void k_bn_apply() {
    long i = blockIdx.x*(long)blockDim.x + threadIdx.x;
    if (i >= 4l*NE) return;
    int c = (int)(i & 127);
    int j = (int)(i / NE);
    float v = g_agg[i];
    float sc = __ldg(&g_bnp[(j*DD + c)*2]);
    float sh = __ldg(&g_bnp[(j*DD + c)*2 + 1]);
    float y = v*sc + sh;
    y = (y > 0.f) ? y : 0.01f*y;
    g_emb[i] += y;
}

// ---------------- relation embedding update: r = r @ Wrt^T + brt -----------
__global__ void k_rels_update(const float* __restrict__ Wrt, const float* __restrict__ brt,
                              const float* __restrict__ rin, float* __restrict__ rout) {
    __shared__ float rs[4*DD];
    int tid = threadIdx.x;
    if (tid < 4*DD) rs[tid] = rin[tid];
    __syncthreads();
    if (tid < 4*DD) {
        int j = tid >> 7, k = tid & 127;
        float acc = __ldg(&brt[k]);
        const float* wr = Wrt + k*DD;
#pragma unroll 4
        for (int m = 0; m < DD; m++) acc += rs[j*DD + m] * __ldg(&wr[m]);
        rout[tid] = acc;
    }
}

// ---------------- QKV GEMM: qkv[l] = stk[l] @ w_in^T + b_in ----------------
// stk[l] = finalEmb[map[l]], map = {3,0,2,1}. BM=32, lane: 4 rows x 12 cols.
__global__ __launch_bounds__(256) void k_qkv_gemm(
    const float* __restrict__ Wg, const float* __restrict__ bg)
{
    extern __shared__ float sm[];
    float* Wsm = sm;                 // [128][388] padded
    float* Xsm = sm + 128*388;       // 32*128
    int l = blockIdx.y;
    const int mp[4] = {3, 0, 2, 1};
    int m = mp[l];
    int r0 = blockIdx.x * 32;
    int tid = threadIdx.x;

    for (int e = tid; e < 384*128; e += 256) {
        int c = e >> 7, k = e & 127;
        Wsm[k*388 + c] = Wg[e];      // transpose: Wsm[k][c] = w_in[c][k]
    }
    for (int e = tid; e < 32*128; e += 256) {
        int r = e >> 7, k = e & 127;
        int gr = r0 + r;
        Xsm[e] = (gr < NN) ? g_agg[((size_t)m*NN + gr)*DD + k] : 0.0f;
    }
    __syncthreads();

    int wid = tid >> 5, lane = tid & 31;
    float acc[4][12];
#pragma unroll
    for (int r = 0; r < 4; r++)
#pragma unroll
        for (int c = 0; c < 12; c++) acc[r][c] = 0.f;
    const float* xb = Xsm + (wid*4)*128;
#pragma unroll 2
    for (int k = 0; k < 128; k++) {
        float4 w0 = *(const float4*)&Wsm[k*388 + lane*4];
        float4 w1 = *(const float4*)&Wsm[k*388 + 128 + lane*4];
        float4 w2 = *(const float4*)&Wsm[k*388 + 256 + lane*4];
#pragma unroll
        for (int r = 0; r < 4; r++) {
            float xv = xb[r*128 + k];
            acc[r][0] += xv*w0.x; acc[r][1] += xv*w0.y; acc[r][2]  += xv*w0.z; acc[r][3]  += xv*w0.w;
            acc[r][4] += xv*w1.x; acc[r][5] += xv*w1.y; acc[r][6]  += xv*w1.z; acc[r][7]  += xv*w1.w;
            acc[r][8] += xv*w2.x; acc[r][9] += xv*w2.y; acc[r][10] += xv*w2.z; acc[r][11] += xv*w2.w;
        }
    }
#pragma unroll
    for (int r = 0; r < 4; r++) {
        int gr = r0 + wid*4 + r;
        if (gr < NN) {
            float* op = g_qkv + ((size_t)l*NN + gr)*384;
#pragma unroll
            for (int p = 0; p < 3; p++) {
                float4 b4 = *(const float4*)&bg[p*128 + lane*4];
                float4 v = make_float4(acc[r][p*4+0] + b4.x, acc[r][p*4+1] + b4.y,
                                       acc[r][p*4+2] + b4.z, acc[r][p*4+3] + b4.w);
                *(float4*)&op[p*128 + lane*4] = v;
            }
        }
    }
}

// ---------------- tiny attention (L=4, 4 heads, hd=32) ---------------------
// one thread per (node, head, l): writes o into g_h[l][node][h*32..]
__global__ __launch_bounds__(256) void k_attn() {
    int t = blockIdx.x * blockDim.x + threadIdx.x;
    if (t >= NN*16) return;
    int node = t >> 4; int sub = t & 15; int h = sub >> 2; int l = sub & 3;
    const float scale = 0.17677669529663687f;   // 1/sqrt(32)
    size_t hb = (size_t)node*384 + h*32;

    const float* qp = g_qkv + (size_t)l*NN*384 + hb;
    float q[32];
#pragma unroll
    for (int i = 0; i < 8; i++) {
        float4 v = *(const float4*)&qp[i*4];
        q[i*4] = v.x*scale; q[i*4+1] = v.y*scale; q[i*4+2] = v.z*scale; q[i*4+3] = v.w*scale;
    }
    float s[4]; float mx = -1e30f;
#pragma unroll
    for (int m = 0; m < 4; m++) {
        const float* kp = g_qkv + (size_t)m*NN*384 + hb + 128;
        float a = 0.f;
#pragma unroll
        for (int i = 0; i < 8; i++) {
            float4 kv = *(const float4*)&kp[i*4];
            a += q[i*4]*kv.x + q[i*4+1]*kv.y + q[i*4+2]*kv.z + q[i*4+3]*kv.w;
        }
        s[m] = a; mx = fmaxf(mx, a);
    }
    float e[4]; float den = 0.f;
#pragma unroll
    for (int m = 0; m < 4; m++) { e[m] = expf(s[m] - mx); den += e[m]; }
    float inv = 1.0f/den;
    float o[32];
#pragma unroll
    for (int i = 0; i < 32; i++) o[i] = 0.f;
#pragma unroll
    for (int m = 0; m < 4; m++) {
        float a = e[m]*inv;
        const float* vp = g_qkv + (size_t)m*NN*384 + hb + 256;
#pragma unroll
        for (int i = 0; i < 8; i++) {
            float4 vv = *(const float4*)&vp[i*4];
            o[i*4] += a*vv.x; o[i*4+1] += a*vv.y; o[i*4+2] += a*vv.z; o[i*4+3] += a*vv.w;
        }
    }
    float* op = g_h + ((size_t)l*NN + node)*DD + h*32;
#pragma unroll
    for (int i = 0; i < 8; i++)
        *(float4*)&op[i*4] = make_float4(o[i*4], o[i*4+1], o[i*4+2], o[i*4+3]);
}

// ---------------- out-proj + alpha fusion: f = a*(o@Wout^T+b) + (1-a)*stk --
__global__ __launch_bounds__(256) void k_outproj(
    const float* __restrict__ Wg, const float* __restrict__ bg,
    const float* __restrict__ alphas)
{
    extern __shared__ float sm[];
    float* Wsm = sm;              // [128][132] padded
    float* Xsm = sm + 128*132;    // 64*128
    int l = blockIdx.y;
    const int mp[4] = {3, 0, 2, 1};
    int m = mp[l];
    int r0 = blockIdx.x * 64;
    int tid = threadIdx.x;

    for (int e = tid; e < 128*128; e += 256) {
        int c = e >> 7, k = e & 127;
        Wsm[k*132 + c] = Wg[e];   // Wsm[k][c] = w_out[c][k]
    }
    for (int e = tid; e < 64*128; e += 256) {
        int r = e >> 7, k = e & 127;
        int gr = r0 + r;
        Xsm[e] = (gr < NN) ? g_h[((size_t)l*NN + gr)*DD + k] : 0.0f;
    }
    __syncthreads();

    int wid = tid >> 5, lane = tid & 31;
    float acc[8][4];
#pragma unroll
    for (int r = 0; r < 8; r++) { acc[r][0]=0.f; acc[r][1]=0.f; acc[r][2]=0.f; acc[r][3]=0.f; }
    const float* xb = Xsm + (wid*8)*128;
#pragma unroll 4
    for (int k = 0; k < 128; k++) {
        float4 wv = *(const float4*)&Wsm[k*132 + lane*4];
#pragma unroll
        for (int r = 0; r < 8; r++) {
            float xv = xb[r*128 + k];
            acc[r][0] += xv*wv.x; acc[r][1] += xv*wv.y;
            acc[r][2] += xv*wv.z; acc[r][3] += xv*wv.w;
        }
    }
    float a = __ldg(&alphas[l]);
    float na = 1.0f - a;
    float4 b4 = *(const float4*)&bg[lane*4];
#pragma unroll
    for (int r = 0; r < 8; r++) {
        int gr = r0 + wid*8 + r;
        if (gr < NN) {
            float4 s4 = *(const float4*)&g_agg[((size_t)m*NN + gr)*DD + lane*4];
            float4 f4 = make_float4(a*(acc[r][0] + b4.x) + na*s4.x,
                                    a*(acc[r][1] + b4.y) + na*s4.y,
                                    a*(acc[r][2] + b4.z) + na*s4.z,
                                    a*(acc[r][3] + b4.w) + na*s4.w);
            *(float4*)&g_emb[((size_t)l*NN + gr)*DD + lane*4] = f4;
        }
    }
}

// ---------------- fusion score: sum_n sum_k leaky(f@Wf^T+bf)*q -------------
__global__ __launch_bounds__(256) void k_score(
    const float* __restrict__ Wg, const float* __restrict__ bg,
    const float* __restrict__ qv)
{
    extern __shared__ float sm[];
    float* Wsm = sm;              // [128][132]
    float* Xsm = sm + 128*132;    // 64*128
    __shared__ float wsum[8];
    int l = blockIdx.y;
    const int slotmap[4] = {0, 1, 3, 2};  // scores stacked (f0,f1,f3,f2)
    int r0 = blockIdx.x * 64;
    int tid = threadIdx.x;

    for (int e = tid; e < 128*128; e += 256) {
        int c = e >> 7, k = e & 127;
        Wsm[k*132 + c] = Wg[e];
    }
    for (int e = tid; e < 64*128; e += 256) {
        int r = e >> 7, k = e & 127;
        int gr = r0 + r;
        Xsm[e] = (gr < NN) ? g_emb[((size_t)l*NN + gr)*DD + k] : 0.0f;
    }
    __syncthreads();

    int wid = tid >> 5, lane = tid & 31;
    float acc[8][4];
#pragma unroll
    for (int r = 0; r < 8; r++) { acc[r][0]=0.f; acc[r][1]=0.f; acc[r][2]=0.f; acc[r][3]=0.f; }
    const float* xb = Xsm + (wid*8)*128;
#pragma unroll 4
    for (int k = 0; k < 128; k++) {
        float4 wv = *(const float4*)&Wsm[k*132 + lane*4];
#pragma unroll
        for (int r = 0; r < 8; r++) {
            float xv = xb[r*128 + k];
            acc[r][0] += xv*wv.x; acc[r][1] += xv*wv.y;
            acc[r][2] += xv*wv.z; acc[r][3] += xv*wv.w;
        }
    }
    float4 b4 = *(const float4*)&bg[lane*4];
    float4 q4 = *(const float4*)&qv[lane*4];
    float lsum = 0.f;
#pragma unroll
    for (int r = 0; r < 8; r++) {
        int gr = r0 + wid*8 + r;
        if (gr < NN) {
            float v0 = acc[r][0] + b4.x; v0 = (v0 > 0.f) ? v0 : 0.01f*v0;
            float v1 = acc[r][1] + b4.y; v1 = (v1 > 0.f) ? v1 : 0.01f*v1;
            float v2 = acc[r][2] + b4.z; v2 = (v2 > 0.f) ? v2 : 0.01f*v2;
            float v3 = acc[r][3] + b4.w; v3 = (v3 > 0.f) ? v3 : 0.01f*v3;
            lsum += v0*q4.x + v1*q4.y + v2*q4.z + v3*q4.w;
        }
    }
#pragma unroll
    for (int o = 16; o > 0; o >>= 1) lsum += __shfl_xor_sync(0xffffffffu, lsum, o);
    if (lane == 0) wsum[wid] = lsum;
    __syncthreads();
    if (tid == 0) {
        float tot = 0.f;
#pragma unroll
        for (int i = 0; i < 8; i++) tot += wsum[i];
        atomicAdd(&g_score[slotmap[l]], tot);
    }
}

__global__ void k_softmax_w() {
    if (threadIdx.x == 0 && blockIdx.x == 0) {
        float s[4]; float mx = -1e30f;
        for (int i = 0; i < 4; i++) { s[i] = g_score[i] / (float)NN; mx = fmaxf(mx, s[i]); }
        float e[4]; float den = 0.f;
        for (int i = 0; i < 4; i++) { e[i] = expf(s[i] - mx); den += e[i]; }
        for (int i = 0; i < 4; i++) g_w[i] = e[i] / den;
    }
}

// ---------------- final region + 5 outputs ---------------------------------
__global__ void k_final(float* __restrict__ out) {
    int i = blockIdx.x * blockDim.x + threadIdx.x;
    if (i >= NE) return;
    int c = i & 127;
    float f0 = g_emb[i], f1 = g_emb[NE + i], f2 = g_emb[2*NE + i], f3 = g_emb[3*NE + i];
    float w0 = __ldg(&g_w[0]), w1 = __ldg(&g_w[1]), w2 = __ldg(&g_w[2]), w3 = __ldg(&g_w[3]);
    // region = w0*n_f + w1*poi_f + w2*s_f + w3*d_f = w0*f0 + w1*f1 + w2*f3 + w3*f2
    float region = w0*f0 + w1*f1 + w2*f3 + w3*f2;
    const float* rf = g_rels[1];   // final rels after 3 ping-pong updates
    out[i]        = region;
    out[NE + i]   = region * __ldg(&rf[3*DD + c]);
    out[2*NE + i] = region * __ldg(&rf[0*DD + c]);
    out[3*NE + i] = region * __ldg(&rf[1*DD + c]);
    out[4*NE + i] = region * __ldg(&rf[2*DD + c]);
}

// ---------------- host launcher --------------------------------------------
extern "C" void kernel_launch(void* const* d_in, const int* in_sizes, int n_in,
                              void* d_out, int out_size) {
    const float* features   = (const float*)d_in[0];
    const float* rel_emb    = (const float*)d_in[1];
    const int*   edge_index = (const int*)  d_in[2];
    const float* W_gcn      = (const float*)d_in[3];
    const float* b_gcn      = (const float*)d_in[4];
    const float* bn_gamma   = (const float*)d_in[5];
    const float* bn_beta    = (const float*)d_in[6];
    const float* W_rt       = (const float*)d_in[7];
    const float* b_rt       = (const float*)d_in[8];
    const float* attn_w_in  = (const float*)d_in[9];
    const float* attn_b_in  = (const float*)d_in[10];
    const float* attn_w_out = (const float*)d_in[11];
    const float* attn_b_out = (const float*)d_in[12];
    const float* alphas     = (const float*)d_in[13];
    const float* fusion_q   = (const float*)d_in[14];
    const float* fusion_w   = (const float*)d_in[15];
    const float* fusion_b   = (const float*)d_in[16];
    float* out = (float*)d_out;

    const int GCN_SMEM  = (128*128 + 64*128) * 4;   // 96 KB
    const int QKV_SMEM  = (128*388 + 32*128) * 4;   // 210 KB
    const int T_SMEM    = (128*132 + 64*128) * 4;   // 98 KB
    cudaFuncSetAttribute(k_gcn_gemm, cudaFuncAttributeMaxDynamicSharedMemorySize, GCN_SMEM);
    cudaFuncSetAttribute(k_qkv_gemm, cudaFuncAttributeMaxDynamicSharedMemorySize, QKV_SMEM);
    cudaFuncSetAttribute(k_outproj,  cudaFuncAttributeMaxDynamicSharedMemorySize, T_SMEM);
    cudaFuncSetAttribute(k_score,    cudaFuncAttributeMaxDynamicSharedMemorySize, T_SMEM);

    // init + CSR build (edge structure shared by all 3 layers)
    k_init_emb<<<(NE + 255)/256, 256>>>(features);
    k_init_small<<<(NB4 + 255)/256, 256>>>(rel_emb);
    k_hist<<<(4*EE + 255)/256, 256>>>(edge_index);
    k_scan1<<<SCAN_BLOCKS, 1024>>>();
    k_scan2<<<1, 32>>>();
    k_scan3<<<(NB4 + 255)/256, 256>>>();
    k_reorder<<<(4*EE + 255)/256, 256>>>(edge_index);

    dim3 ggrid((NN + 63)/64, 4);
    dim3 agrid((NN + 7)/8, 4);
    dim3 bngrid(128, 4);
    int bnchunk = (NN + 127)/128;

    // rels ping-pong: layer0 reads buf0 -> writes buf1; layer1 buf1->buf0; layer2 buf0->buf1
    float* r0p; float* r1p;
    cudaGetSymbolAddress((void**)&r0p, g_rels);   // buf0
    r1p = r0p + 4*DD;                             // buf1

    const float* rin[3]  = { r0p, r1p, r0p };
    float*       rout[3] = { r1p, r0p, r1p };

    for (int i = 0; i < 2; i++) {
        k_gcn_gemm<<<ggrid, 256, GCN_SMEM>>>(W_gcn + i*DD*DD, rin[i]);
        k_gather<<<agrid, 256>>>(b_gcn + i*DD);
        k_zero_stats<<<1, 1024>>>();
        k_bn_stats<<<bngrid, 128>>>(bnchunk);
        k_bn_finalize<<<1, 512>>>(bn_gamma + i*DD, bn_beta + i*DD);
        k_bn_apply<<<(4*NE + 255)/256, 256>>>();
        k_rels_update<<<1, 512>>>(W_rt + i*DD*DD, b_rt + i*DD, rin[i], rout[i]);
    }
    // final GCN layer (no BN/residual) -> result in g_agg
    k_gcn_gemm<<<ggrid, 256, GCN_SMEM>>>(W_gcn + 2*DD*DD, rin[2]);
    k_gather<<<agrid, 256>>>(b_gcn + 2*DD);
    k_rels_update<<<1, 512>>>(W_rt + 2*DD*DD, b_rt + 2*DD, rin[2], rout[2]);

    // MHA + fusion
    dim3 qgrid((NN + 31)/32, 4);
    k_qkv_gemm<<<qgrid, 256, QKV_SMEM>>>(attn_w_in, attn_b_in);
    k_attn<<<(NN*16 + 255)/256, 256>>>();
    k_outproj<<<ggrid, 256, T_SMEM>>>(attn_w_out, attn_b_out, alphas);
    k_score<<<ggrid, 256, T_SMEM>>>(fusion_w, fusion_b, fusion_q);
    k_softmax_w<<<1, 32>>>();
    k_final<<<(NE + 255)/256, 256>>>(out);
}

// round 6
// speedup vs baseline: 1.3818x; 1.0386x over previous
#include <cuda_runtime.h>
#include <math.h>

#define NN 50000
#define DD 128
#define EE 400000
#define NE (NN*DD)
#define NB4 (4*NN)
#define SCAN_BLOCKS ((NB4 + 1023)/1024)

typedef unsigned long long ull;
#define FMA2(acc, a, b) asm("fma.rn.f32x2 %0, %1, %2, %0;" : "+l"(acc) : "l"(a), "l"(b))
#define UNPK(lo, hi, v) asm("mov.b64 {%0, %1}, %2;" : "=f"(lo), "=f"(hi) : "l"(v))

// ---------------- scratch (static device memory; no allocations) ----------
__device__ __align__(16) float g_emb[4*NE];
__device__ __align__(16) float g_h[4*NE];
__device__ __align__(16) float g_agg[4*NE];
__device__ __align__(16) float g_qkv[4ll*NN*384];
__device__ __align__(16) float g_dinv[NB4];
__device__ __align__(16) int   g_cnt[NB4];
__device__ __align__(16) int   g_off[NB4];
__device__ __align__(16) int   g_cur[NB4];
__device__ __align__(16) int   g_bsum[SCAN_BLOCKS];
__device__ __align__(16) int   g_esrc[4*EE];
__device__ __align__(16) float g_enorm[4*EE];    // per-edge dinv_s*dinv_d
__device__ __align__(16) float g_rels[2][4*DD];
__device__ __align__(16) float g_stats[4*DD*2];
__device__ __align__(16) float g_bnp[4*DD*2];
__device__ float g_score[4];
__device__ float g_w[4];

// ---------------- init kernels --------------------------------------------
__global__ void k_init_emb(const float* __restrict__ feat) {
    int i = blockIdx.x * blockDim.x + threadIdx.x;
    if (i < NE) {
        float v = feat[i];
        g_emb[i] = v; g_emb[NE + i] = v; g_emb[2*NE + i] = v; g_emb[3*NE + i] = v;
    }
}

__global__ void k_init_small(const float* __restrict__ rel_emb) {
    int i = blockIdx.x * blockDim.x + threadIdx.x;
    if (i < NB4) g_cnt[i] = 0;
    if (i < 4*DD) {
        int j = i >> 7, c = i & 127;
        int p = (j + 3) & 3;
        g_rels[0][i] = rel_emb[p*DD + c];
    }
    if (i < 4) g_score[i] = 0.0f;
}

// ---------------- CSR build: histogram -> scan -> reorder ------------------
__global__ void k_hist(const int* __restrict__ ei) {
    int t = blockIdx.x * blockDim.x + threadIdx.x;
    if (t >= 4*EE) return;
    int j = t / EE; int e = t - j*EE;
    int p = (j + 3) & 3;
    int dst = ei[(size_t)p*2*EE + EE + e];
    atomicAdd(&g_cnt[j*NN + dst], 1);
}

__global__ __launch_bounds__(1024) void k_scan1() {
    __shared__ int s[1024];
    int i = blockIdx.x * 1024 + threadIdx.x;
    int v = (i < NB4) ? g_cnt[i] : 0;
    s[threadIdx.x] = v;
    __syncthreads();
    for (int o = 1; o < 1024; o <<= 1) {
        int t = (threadIdx.x >= o) ? s[threadIdx.x - o] : 0;
        __syncthreads();
        s[threadIdx.x] += t;
        __syncthreads();
    }
    if (i < NB4) g_off[i] = s[threadIdx.x] - v;   // exclusive
    if (threadIdx.x == 1023) g_bsum[blockIdx.x] = s[1023];
}

__global__ void k_scan2() {
    if (threadIdx.x == 0) {
        int acc = 0;
        for (int b = 0; b < SCAN_BLOCKS; b++) { int v = g_bsum[b]; g_bsum[b] = acc; acc += v; }
    }
}

__global__ void k_scan3() {
    int i = blockIdx.x * blockDim.x + threadIdx.x;
    if (i < NB4) {
        int o = g_off[i] + g_bsum[i >> 10];
        g_off[i] = o; g_cur[i] = o;
        g_dinv[i] = rsqrtf((float)g_cnt[i] + 1.0f);
    }
}

__global__ void k_reorder(const int* __restrict__ ei) {
    int t = blockIdx.x * blockDim.x + threadIdx.x;
    if (t >= 4*EE) return;
    int j = t / EE; int e = t - j*EE;
    int p = (j + 3) & 3;
    const int* base = ei + (size_t)p*2*EE;
    int src = __ldg(&base[e]);
    int dst = __ldg(&base[EE + e]);
    int pos = atomicAdd(&g_cur[j*NN + dst], 1);
    g_esrc[pos] = src;
    g_enorm[pos] = __ldg(&g_dinv[j*NN + src]) * __ldg(&g_dinv[j*NN + dst]);
}

// ---------------- GCN GEMM: h = (emb*rels) @ W (FFMA2 packed over k) -------
// Wsm2[kk][c] = (W[2kk][c], W[2kk+1][c]); X row-major, pairs contiguous.
__global__ __launch_bounds__(256) void k_gcn_gemm(
    const float* __restrict__ Wg, const float* __restrict__ rels)
{
    extern __shared__ float sm[];
    float* Wsm = sm;               // 64*128 float2 = 16384 floats
    float* Xsm = sm + 128*128;     // 64*128
    int j = blockIdx.y;
    int r0 = blockIdx.x * 64;
    int tid = threadIdx.x;

    for (int e = tid; e < 64*128; e += 256) {
        int kk = e >> 7, c = e & 127;
        ((float2*)Wsm)[e] = make_float2(Wg[(2*kk)*128 + c], Wg[(2*kk+1)*128 + c]);
    }
    const float* rrow = rels + j*DD;
    for (int e = tid; e < 64*128; e += 256) {
        int r = e >> 7, k = e & 127;
        int gr = r0 + r;
        Xsm[e] = (gr < NN) ? g_emb[((size_t)j*NN + gr)*DD + k] * __ldg(&rrow[k]) : 0.0f;
    }
    __syncthreads();

    int wid = tid >> 5, lane = tid & 31;
    ull acc2[8][4];
#pragma unroll
    for (int r = 0; r < 8; r++) { acc2[r][0]=0ull; acc2[r][1]=0ull; acc2[r][2]=0ull; acc2[r][3]=0ull; }
    const float* xb = Xsm + (wid*8)*128;
    const ull* wp = (const ull*)Wsm;
#pragma unroll 2
    for (int kk = 0; kk < 64; kk++) {
        ulonglong2 wa = *(const ulonglong2*)&wp[kk*128 + lane*4];
        ulonglong2 wb = *(const ulonglong2*)&wp[kk*128 + lane*4 + 2];
#pragma unroll
        for (int r = 0; r < 8; r++) {
            ull xv = *(const ull*)&xb[r*128 + 2*kk];
            FMA2(acc2[r][0], xv, wa.x); FMA2(acc2[r][1], xv, wa.y);
            FMA2(acc2[r][2], xv, wb.x); FMA2(acc2[r][3], xv, wb.y);
        }
    }
#pragma unroll
    for (int r = 0; r < 8; r++) {
        int gr = r0 + wid*8 + r;
        if (gr < NN) {
            float lo, hi, v[4];
#pragma unroll
            for (int c = 0; c < 4; c++) { UNPK(lo, hi, acc2[r][c]); v[c] = lo + hi; }
            *(float4*)&g_h[((size_t)j*NN + gr)*DD + lane*4] = make_float4(v[0], v[1], v[2], v[3]);
        }
    }
}

// ---------------- gather: agg = b + h[dst]*d2 + sum h[src]*norm ------------
__global__ __launch_bounds__(256) void k_gather(const float* __restrict__ bg) {
    int j = blockIdx.y;
    int wid = threadIdx.x >> 5, lane = threadIdx.x & 31;
    int dst = blockIdx.x*8 + wid;
    if (dst >= NN) return;
    int idx = j*NN + dst;
    int beg = __ldg(&g_off[idx]);
    int cnt = __ldg(&g_cnt[idx]);
    float dd = __ldg(&g_dinv[idx]);
    float d2 = dd*dd;

    float4 b4 = *(const float4*)&bg[lane*4];
    float4 hd = *(const float4*)&g_h[((size_t)idx)*DD + lane*4];
    float ax = b4.x + hd.x*d2, ay = b4.y + hd.y*d2;
    float az = b4.z + hd.z*d2, aw = b4.w + hd.w*d2;

    int t = 0;
    for (; t + 2 <= cnt; t += 2) {
        int s0 = __ldg(&g_esrc[beg + t]);
        int s1 = __ldg(&g_esrc[beg + t + 1]);
        float n0 = __ldg(&g_enorm[beg + t]);
        float n1 = __ldg(&g_enorm[beg + t + 1]);
        float4 h0 = *(const float4*)&g_h[((size_t)j*NN + s0)*DD + lane*4];
        float4 h1 = *(const float4*)&g_h[((size_t)j*NN + s1)*DD + lane*4];
        ax += h0.x*n0 + h1.x*n1; ay += h0.y*n0 + h1.y*n1;
        az += h0.z*n0 + h1.z*n1; aw += h0.w*n0 + h1.w*n1;
    }
    if (t < cnt) {
        int s0 = __ldg(&g_esrc[beg + t]);
        float n0 = __ldg(&g_enorm[beg + t]);
        float4 h0 = *(const float4*)&g_h[((size_t)j*NN + s0)*DD + lane*4];
        ax += h0.x*n0; ay += h0.y*n0; az += h0.z*n0; aw += h0.w*n0;
    }
    *(float4*)&g_agg[((size_t)idx)*DD + lane*4] = make_float4(ax, ay, az, aw);
}

// ---------------- BatchNorm ------------------------------------------------
__global__ void k_zero_stats() { int i = threadIdx.x; if (i < 4*DD*2) g_stats[i] = 0.f; }

__global__ void k_bn_stats(int chunk) {
    int j = blockIdx.y, c = threadIdx.x;
    int rs = blockIdx.x * chunk;
    int re = min(rs + chunk, NN);
    float s = 0.f, s2 = 0.f;
    const float* base = g_agg + (size_t)j*NE;
    for (int r = rs; r < re; r++) {
        float v = base[(size_t)r*DD + c];
        s += v; s2 += v*v;
    }
    atomicAdd(&g_stats[(j*DD + c)*2], s);
    atomicAdd(&g_stats[(j*DD + c)*2 + 1], s2);
}

__global__ void k_bn_finalize(const float* __restrict__ gamma, const float* __restrict__ beta) {
    int i = threadIdx.x;
    if (i < 4*DD) {
        int c = i & 127;
        float s = g_stats[i*2], s2 = g_stats[i*2 + 1];
        float mean = s / (float)NN;
        float var = s2 / (float)NN - mean*mean;
        float sc = __ldg(&gamma[c]) * rsqrtf(var + 1e-5f);
        g_bnp[i*2] = sc;
        g_bnp[i*2 + 1] = __ldg(&beta[c]) - mean*sc;
    }
}

__global__ void k_bn_apply() {
    long i = blockIdx.x*(long)blockDim.x + threadIdx.x;
    if (i >= 4l*NE) return;
    int c = (int)(i & 127);
    int j = (int)(i / NE);
    float v = g_agg[i];
    float sc = __ldg(&g_bnp[(j*DD + c)*2]);
    float sh = __ldg(&g_bnp[(j*DD + c)*2 + 1]);
    float y = v*sc + sh;
    y = (y > 0.f) ? y : 0.01f*y;
    g_emb[i] += y;
}

// ---------------- relation embedding update: r = r @ Wrt^T + brt -----------
__global__ void k_rels_update(const float* __restrict__ Wrt, const float* __restrict__ brt,
                              const float* __restrict__ rin, float* __restrict__ rout) {
    __shared__ float rs[4*DD];
    int tid = threadIdx.x;
    if (tid < 4*DD) rs[tid] = rin[tid];
    __syncthreads();
    if (tid < 4*DD) {
        int j = tid >> 7, k = tid & 127;
        float acc = __ldg(&brt[k]);
        const float* wr = Wrt + k*DD;
#pragma unroll 4
        for (int m = 0; m < DD; m++) acc += rs[j*DD + m] * __ldg(&wr[m]);
        rout[tid] = acc;
    }
}

// ---------------- QKV GEMM: qkv[l] = stk[l] @ w_in^T + b_in (FFMA2) --------
// Wsm2[kk][c] = (Wg[c][2kk], Wg[c][2kk+1]), stride 385 float2 (store-conflict pad).
#define QS 385
__global__ __launch_bounds__(256) void k_qkv_gemm(
    const float* __restrict__ Wg, const float* __restrict__ bg)
{
    extern __shared__ float sm[];
    float* Wsm = sm;                 // 64*QS float2
    float* Xsm = sm + 64*QS*2;       // 32*128
    int l = blockIdx.y;
    const int mp[4] = {3, 0, 2, 1};
    int m = mp[l];
    int r0 = blockIdx.x * 32;
    int tid = threadIdx.x;

    for (int e = tid; e < 384*64; e += 256) {
        int c = e >> 6, kk = e & 63;                 // gmem-coalesced over kk
        float2 v = *(const float2*)&Wg[c*128 + 2*kk];
        ((float2*)Wsm)[kk*QS + c] = v;
    }
    for (int e = tid; e < 32*128; e += 256) {
        int r = e >> 7, k = e & 127;
        int gr = r0 + r;
        Xsm[e] = (gr < NN) ? g_agg[((size_t)m*NN + gr)*DD + k] : 0.0f;
    }
    __syncthreads();

    int wid = tid >> 5, lane = tid & 31;
    ull acc2[4][12];
#pragma unroll
    for (int r = 0; r < 4; r++)
#pragma unroll
        for (int c = 0; c < 12; c++) acc2[r][c] = 0ull;
    const float* xb = Xsm + (wid*4)*128;
    const ull* wp = (const ull*)Wsm;
#pragma unroll 2
    for (int kk = 0; kk < 64; kk++) {
        ull wv[12];
#pragma unroll
        for (int p = 0; p < 3; p++)
#pragma unroll
            for (int c = 0; c < 4; c++)
                wv[p*4 + c] = wp[kk*QS + p*128 + lane*4 + c];
#pragma unroll
        for (int r = 0; r < 4; r++) {
            ull xv = *(const ull*)&xb[r*128 + 2*kk];
#pragma unroll
            for (int c = 0; c < 12; c++) FMA2(acc2[r][c], xv, wv[c]);
        }
    }
#pragma unroll
    for (int r = 0; r < 4; r++) {
        int gr = r0 + wid*4 + r;
        if (gr < NN) {
            float* op = g_qkv + ((size_t)l*NN + gr)*384;
#pragma unroll
            for (int p = 0; p < 3; p++) {
                float4 b4 = *(const float4*)&bg[p*128 + lane*4];
                float lo, hi, v[4];
#pragma unroll
                for (int c = 0; c < 4; c++) { UNPK(lo, hi, acc2[r][p*4+c]); v[c] = lo + hi; }
                *(float4*)&op[p*128 + lane*4] = make_float4(v[0]+b4.x, v[1]+b4.y, v[2]+b4.z, v[3]+b4.w);
            }
        }
    }
}

// ---------------- tiny attention (L=4, 4 heads, hd=32) ---------------------
__global__ __launch_bounds__(256) void k_attn() {
    int t = blockIdx.x * blockDim.x + threadIdx.x;
    if (t >= NN*16) return;
    int node = t >> 4; int sub = t & 15; int h = sub >> 2; int l = sub & 3;
    const float scale = 0.17677669529663687f;   // 1/sqrt(32)
    size_t hb = (size_t)node*384 + h*32;

    const float* qp = g_qkv + (size_t)l*NN*384 + hb;
    float q[32];
#pragma unroll
    for (int i = 0; i < 8; i++) {
        float4 v = *(const float4*)&qp[i*4];
        q[i*4] = v.x*scale; q[i*4+1] = v.y*scale; q[i*4+2] = v.z*scale; q[i*4+3] = v.w*scale;
    }
    float s[4]; float mx = -1e30f;
#pragma unroll
    for (int m = 0; m < 4; m++) {
        const float* kp = g_qkv + (size_t)m*NN*384 + hb + 128;
        float a = 0.f;
#pragma unroll
        for (int i = 0; i < 8; i++) {
            float4 kv = *(const float4*)&kp[i*4];
            a += q[i*4]*kv.x + q[i*4+1]*kv.y + q[i*4+2]*kv.z + q[i*4+3]*kv.w;
        }
        s[m] = a; mx = fmaxf(mx, a);
    }
    float e[4]; float den = 0.f;
#pragma unroll
    for (int m = 0; m < 4; m++) { e[m] = expf(s[m] - mx); den += e[m]; }
    float inv = 1.0f/den;
    float o[32];
#pragma unroll
    for (int i = 0; i < 32; i++) o[i] = 0.f;
#pragma unroll
    for (int m = 0; m < 4; m++) {
        float a = e[m]*inv;
        const float* vp = g_qkv + (size_t)m*NN*384 + hb + 256;
#pragma unroll
        for (int i = 0; i < 8; i++) {
            float4 vv = *(const float4*)&vp[i*4];
            o[i*4] += a*vv.x; o[i*4+1] += a*vv.y; o[i*4+2] += a*vv.z; o[i*4+3] += a*vv.w;
        }
    }
    float* op = g_h + ((size_t)l*NN + node)*DD + h*32;
#pragma unroll
    for (int i = 0; i < 8; i++)
        *(float4*)&op[i*4] = make_float4(o[i*4], o[i*4+1], o[i*4+2], o[i*4+3]);
}

// ---------------- out-proj + alpha fusion (FFMA2, W^T pair layout) ---------
#define TS 129
__global__ __launch_bounds__(256) void k_outproj(
    const float* __restrict__ Wg, const float* __restrict__ bg,
    const float* __restrict__ alphas)
{
    extern __shared__ float sm[];
    float* Wsm = sm;              // 64*TS float2
    float* Xsm = sm + 64*TS*2;    // 64*128
    int l = blockIdx.y;
    const int mp[4] = {3, 0, 2, 1};
    int m = mp[l];
    int r0 = blockIdx.x * 64;
    int tid = threadIdx.x;

    for (int e = tid; e < 128*64; e += 256) {
        int c = e >> 6, kk = e & 63;
        float2 v = *(const float2*)&Wg[c*128 + 2*kk];
        ((float2*)Wsm)[kk*TS + c] = v;
    }
    for (int e = tid; e < 64*128; e += 256) {
        int r = e >> 7, k = e & 127;
        int gr = r0 + r;
        Xsm[e] = (gr < NN) ? g_h[((size_t)l*NN + gr)*DD + k] : 0.0f;
    }
    __syncthreads();

    int wid = tid >> 5, lane = tid & 31;
    ull acc2[8][4];
#pragma unroll
    for (int r = 0; r < 8; r++) { acc2[r][0]=0ull; acc2[r][1]=0ull; acc2[r][2]=0ull; acc2[r][3]=0ull; }
    const float* xb = Xsm + (wid*8)*128;
    const ull* wp = (const ull*)Wsm;
#pragma unroll 2
    for (int kk = 0; kk < 64; kk++) {
        ull w0 = wp[kk*TS + lane*4 + 0];
        ull w1 = wp[kk*TS + lane*4 + 1];
        ull w2 = wp[kk*TS + lane*4 + 2];
        ull w3 = wp[kk*TS + lane*4 + 3];
#pragma unroll
        for (int r = 0; r < 8; r++) {
            ull xv = *(const ull*)&xb[r*128 + 2*kk];
            FMA2(acc2[r][0], xv, w0); FMA2(acc2[r][1], xv, w1);
            FMA2(acc2[r][2], xv, w2); FMA2(acc2[r][3], xv, w3);
        }
    }
    float a = __ldg(&alphas[l]);
    float na = 1.0f - a;
    float4 b4 = *(const float4*)&bg[lane*4];
#pragma unroll
    for (int r = 0; r < 8; r++) {
        int gr = r0 + wid*8 + r;
        if (gr < NN) {
            float4 s4 = *(const float4*)&g_agg[((size_t)m*NN + gr)*DD + lane*4];
            float lo, hi, v[4];
#pragma unroll
            for (int c = 0; c < 4; c++) { UNPK(lo, hi, acc2[r][c]); v[c] = lo + hi; }
            float4 f4 = make_float4(a*(v[0] + b4.x) + na*s4.x,
                                    a*(v[1] + b4.y) + na*s4.y,
                                    a*(v[2] + b4.z) + na*s4.z,
                                    a*(v[3] + b4.w) + na*s4.w);
            *(float4*)&g_emb[((size_t)l*NN + gr)*DD + lane*4] = f4;
        }
    }
}

// ---------------- fusion score (FFMA2, W^T pair layout) --------------------
__global__ __launch_bounds__(256) void k_score(
    const float* __restrict__ Wg, const float* __restrict__ bg,
    const float* __restrict__ qv)
{
    extern __shared__ float sm[];
    float* Wsm = sm;              // 64*TS float2
    float* Xsm = sm + 64*TS*2;    // 64*128
    __shared__ float wsum[8];
    int l = blockIdx.y;
    const int slotmap[4] = {0, 1, 3, 2};
    int r0 = blockIdx.x * 64;
    int tid = threadIdx.x;

    for (int e = tid; e < 128*64; e += 256) {
        int c = e >> 6, kk = e & 63;
        float2 v = *(const float2*)&Wg[c*128 + 2*kk];
        ((float2*)Wsm)[kk*TS + c] = v;
    }
    for (int e = tid; e < 64*128; e += 256) {
        int r = e >> 7, k = e & 127;
        int gr = r0 + r;
        Xsm[e] = (gr < NN) ? g_emb[((size_t)l*NN + gr)*DD + k] : 0.0f;
    }
    __syncthreads();

    int wid = tid >> 5, lane = tid & 31;
    ull acc2[8][4];
#pragma unroll
    for (int r = 0; r < 8; r++) { acc2[r][0]=0ull; acc2[r][1]=0ull; acc2[r][2]=0ull; acc2[r][3]=0ull; }
    const float* xb = Xsm + (wid*8)*128;
    const ull* wp = (const ull*)Wsm;
#pragma unroll 2
    for (int kk = 0; kk < 64; kk++) {
        ull w0 = wp[kk*TS + lane*4 + 0];
        ull w1 = wp[kk*TS + lane*4 + 1];
        ull w2 = wp[kk*TS + lane*4 + 2];
        ull w3 = wp[kk*TS + lane*4 + 3];
#pragma unroll
        for (int r = 0; r < 8; r++) {
            ull xv = *(const ull*)&xb[r*128 + 2*kk];
            FMA2(acc2[r][0], xv, w0); FMA2(acc2[r][1], xv, w1);
            FMA2(acc2[r][2], xv, w2); FMA2(acc2[r][3], xv, w3);
        }
    }
    float4 b4 = *(const float4*)&bg[lane*4];
    float4 q4 = *(const float4*)&qv[lane*4];
    float lsum = 0.f;
#pragma unroll
    for (int r = 0; r < 8; r++) {
        int gr = r0 + wid*8 + r;
        if (gr < NN) {
            float lo, hi, v[4];
#pragma unroll
            for (int c = 0; c < 4; c++) { UNPK(lo, hi, acc2[r][c]); v[c] = lo + hi; }
            float v0 = v[0] + b4.x; v0 = (v0 > 0.f) ? v0 : 0.01f*v0;
            float v1 = v[1] + b4.y; v1 = (v1 > 0.f) ? v1 : 0.01f*v1;
            float v2 = v[2] + b4.z; v2 = (v2 > 0.f) ? v2 : 0.01f*v2;
            float v3 = v[3] + b4.w; v3 = (v3 > 0.f) ? v3 : 0.01f*v3;
            lsum += v0*q4.x + v1*q4.y + v2*q4.z + v3*q4.w;
        }
    }
#pragma unroll
    for (int o = 16; o > 0; o >>= 1) lsum += __shfl_xor_sync(0xffffffffu, lsum, o);
    if (lane == 0) wsum[wid] = lsum;
    __syncthreads();
    if (tid == 0) {
        float tot = 0.f;
#pragma unroll
        for (int i = 0; i < 8; i++) tot += wsum[i];
        atomicAdd(&g_score[slotmap[l]], tot);
    }
}

__global__ void k_softmax_w() {
    if (threadIdx.x == 0 && blockIdx.x == 0) {
        float s[4]; float mx = -1e30f;
        for (int i = 0; i < 4; i++) { s[i] = g_score[i] / (float)NN; mx = fmaxf(mx, s[i]); }
        float e[4]; float den = 0.f;
        for (int i = 0; i < 4; i++) { e[i] = expf(s[i] - mx); den += e[i]; }
        for (int i = 0; i < 4; i++) g_w[i] = e[i] / den;
    }
}

// ---------------- final region + 5 outputs ---------------------------------
__global__ void k_final(float* __restrict__ out) {
    int i = blockIdx.x * blockDim.x + threadIdx.x;
    if (i >= NE) return;
    int c = i & 127;
    float f0 = g_emb[i], f1 = g_emb[NE + i], f2 = g_emb[2*NE + i], f3 = g_emb[3*NE + i];
    float w0 = __ldg(&g_w[0]), w1 = __ldg(&g_w[1]), w2 = __ldg(&g_w[2]), w3 = __ldg(&g_w[3]);
    float region = w0*f0 + w1*f1 + w2*f3 + w3*f2;
    const float* rf = g_rels[1];   // final rels after 3 ping-pong updates
    out[i]        = region;
    out[NE + i]   = region * __ldg(&rf[3*DD + c]);
    out[2*NE + i] = region * __ldg(&rf[0*DD + c]);
    out[3*NE + i] = region * __ldg(&rf[1*DD + c]);
    out[4*NE + i] = region * __ldg(&rf[2*DD + c]);
}

// ---------------- host launcher --------------------------------------------
extern "C" void kernel_launch(void* const* d_in, const int* in_sizes, int n_in,
                              void* d_out, int out_size) {
    const float* features   = (const float*)d_in[0];
    const float* rel_emb    = (const float*)d_in[1];
    const int*   edge_index = (const int*)  d_in[2];
    const float* W_gcn      = (const float*)d_in[3];
    const float* b_gcn      = (const float*)d_in[4];
    const float* bn_gamma   = (const float*)d_in[5];
    const float* bn_beta    = (const float*)d_in[6];
    const float* W_rt       = (const float*)d_in[7];
    const float* b_rt       = (const float*)d_in[8];
    const float* attn_w_in  = (const float*)d_in[9];
    const float* attn_b_in  = (const float*)d_in[10];
    const float* attn_w_out = (const float*)d_in[11];
    const float* attn_b_out = (const float*)d_in[12];
    const float* alphas     = (const float*)d_in[13];
    const float* fusion_q   = (const float*)d_in[14];
    const float* fusion_w   = (const float*)d_in[15];
    const float* fusion_b   = (const float*)d_in[16];
    float* out = (float*)d_out;

    const int GCN_SMEM  = (64*128*2 + 64*128) * 4;     // 96 KB
    const int QKV_SMEM  = (64*QS*2 + 32*128) * 4;      // ~213 KB
    const int T_SMEM    = (64*TS*2 + 64*128) * 4;      // ~98.5 KB
    cudaFuncSetAttribute(k_gcn_gemm, cudaFuncAttributeMaxDynamicSharedMemorySize, GCN_SMEM);
    cudaFuncSetAttribute(k_qkv_gemm, cudaFuncAttributeMaxDynamicSharedMemorySize, QKV_SMEM);
    cudaFuncSetAttribute(k_outproj,  cudaFuncAttributeMaxDynamicSharedMemorySize, T_SMEM);
    cudaFuncSetAttribute(k_score,    cudaFuncAttributeMaxDynamicSharedMemorySize, T_SMEM);

    // init + CSR build (edge structure shared by all 3 layers)
    k_init_emb<<<(NE + 255)/256, 256>>>(features);
    k_init_small<<<(NB4 + 255)/256, 256>>>(rel_emb);
    k_hist<<<(4*EE + 255)/256, 256>>>(edge_index);
    k_scan1<<<SCAN_BLOCKS, 1024>>>();
    k_scan2<<<1, 32>>>();
    k_scan3<<<(NB4 + 255)/256, 256>>>();
    k_reorder<<<(4*EE + 255)/256, 256>>>(edge_index);

    dim3 ggrid((NN + 63)/64, 4);
    dim3 agrid((NN + 7)/8, 4);
    dim3 bngrid(128, 4);
    int bnchunk = (NN + 127)/128;

    float* r0p; float* r1p;
    cudaGetSymbolAddress((void**)&r0p, g_rels);   // buf0
    r1p = r0p + 4*DD;                             // buf1

    const float* rin[3]  = { r0p, r1p, r0p };
    float*       rout[3] = { r1p, r0p, r1p };

    for (int i = 0; i < 2; i++) {
        k_gcn_gemm<<<ggrid, 256, GCN_SMEM>>>(W_gcn + i*DD*DD, rin[i]);
        k_gather<<<agrid, 256>>>(b_gcn + i*DD);
        k_zero_stats<<<1, 1024>>>();
        k_bn_stats<<<bngrid, 128>>>(bnchunk);
        k_bn_finalize<<<1, 512>>>(bn_gamma + i*DD, bn_beta + i*DD);
        k_bn_apply<<<(4*NE + 255)/256, 256>>>();
        k_rels_update<<<1, 512>>>(W_rt + i*DD*DD, b_rt + i*DD, rin[i], rout[i]);
    }
    k_gcn_gemm<<<ggrid, 256, GCN_SMEM>>>(W_gcn + 2*DD*DD, rin[2]);
    k_gather<<<agrid, 256>>>(b_gcn + 2*DD);
    k_rels_update<<<1, 512>>>(W_rt + 2*DD*DD, b_rt + 2*DD, rin[2], rout[2]);

    // MHA + fusion
    dim3 qgrid((NN + 31)/32, 4);
    k_qkv_gemm<<<qgrid, 256, QKV_SMEM>>>(attn_w_in, attn_b_in);
    k_attn<<<(NN*16 + 255)/256, 256>>>();
    k_outproj<<<ggrid, 256, T_SMEM>>>(attn_w_out, attn_b_out, alphas);
    k_score<<<ggrid, 256, T_SMEM>>>(fusion_w, fusion_b, fusion_q);
    k_softmax_w<<<1, 32>>>();
    k_final<<<(NE + 255)/256, 256>>>(out);
}

// round 10
// speedup vs baseline: 1.4082x; 1.0192x over previous
#include <cuda_runtime.h>
#include <math.h>

#define NN 50000
#define DD 128
#define EE 400000
#define NE (NN*DD)
#define NB4 (4*NN)
#define SCAN_BLOCKS ((NB4 + 1023)/1024)

typedef unsigned long long ull;
#define FMA2(acc, a, b) asm("fma.rn.f32x2 %0, %1, %2, %0;" : "+l"(acc) : "l"(a), "l"(b))
#define UNPK(lo, hi, v) asm("mov.b64 {%0, %1}, %2;" : "=f"(lo), "=f"(hi) : "l"(v))

// ---------------- scratch (static device memory; no allocations) ----------
__device__ __align__(16) float g_emb[4*NE];
__device__ __align__(16) float g_h[4*NE];
__device__ __align__(16) float g_agg[4*NE];
__device__ __align__(16) float g_dinv[NB4];
__device__ __align__(16) int   g_cnt[NB4];
__device__ __align__(16) int   g_off[NB4];
__device__ __align__(16) int   g_cur[NB4];
__device__ __align__(16) int   g_bsum[SCAN_BLOCKS];
__device__ __align__(16) int   g_esrc[4*EE];
__device__ __align__(16) float g_enorm[4*EE];    // per-edge dinv_s*dinv_d
__device__ __align__(16) float g_rels[2][4*DD];
__device__ __align__(16) float g_stats[4*DD*2];
__device__ __align__(16) float g_bnp[4*DD*2];
__device__ float g_score[4];
__device__ float g_w[4];

// ---------------- init kernels --------------------------------------------
__global__ void k_init_emb(const float* __restrict__ feat) {
    int i = blockIdx.x * blockDim.x + threadIdx.x;
    if (i < NE) {
        float v = feat[i];
        g_emb[i] = v; g_emb[NE + i] = v; g_emb[2*NE + i] = v; g_emb[3*NE + i] = v;
    }
}

__global__ void k_init_small(const float* __restrict__ rel_emb) {
    int i = blockIdx.x * blockDim.x + threadIdx.x;
    if (i < NB4) g_cnt[i] = 0;
    if (i < 4*DD) {
        int j = i >> 7, c = i & 127;
        int p = (j + 3) & 3;
        g_rels[0][i] = rel_emb[p*DD + c];
    }
    if (i < 4) g_score[i] = 0.0f;
}

// ---------------- CSR build: histogram -> scan -> reorder ------------------
__global__ void k_hist(const int* __restrict__ ei) {
    int t = blockIdx.x * blockDim.x + threadIdx.x;
    if (t >= 4*EE) return;
    int j = t / EE; int e = t - j*EE;
    int p = (j + 3) & 3;
    int dst = ei[(size_t)p*2*EE + EE + e];
    atomicAdd(&g_cnt[j*NN + dst], 1);
}

__global__ __launch_bounds__(1024) void k_scan1() {
    __shared__ int s[1024];
    int i = blockIdx.x * 1024 + threadIdx.x;
    int v = (i < NB4) ? g_cnt[i] : 0;
    s[threadIdx.x] = v;
    __syncthreads();
    for (int o = 1; o < 1024; o <<= 1) {
        int t = (threadIdx.x >= o) ? s[threadIdx.x - o] : 0;
        __syncthreads();
        s[threadIdx.x] += t;
        __syncthreads();
    }
    if (i < NB4) g_off[i] = s[threadIdx.x] - v;   // exclusive
    if (threadIdx.x == 1023) g_bsum[blockIdx.x] = s[1023];
}

__global__ void k_scan2() {
    if (threadIdx.x == 0) {
        int acc = 0;
        for (int b = 0; b < SCAN_BLOCKS; b++) { int v = g_bsum[b]; g_bsum[b] = acc; acc += v; }
    }
}

__global__ void k_scan3() {
    int i = blockIdx.x * blockDim.x + threadIdx.x;
    if (i < NB4) {
        int o = g_off[i] + g_bsum[i >> 10];
        g_off[i] = o; g_cur[i] = o;
        g_dinv[i] = rsqrtf((float)g_cnt[i] + 1.0f);
    }
}

__global__ void k_reorder(const int* __restrict__ ei) {
    int t = blockIdx.x * blockDim.x + threadIdx.x;
    if (t >= 4*EE) return;
    int j = t / EE; int e = t - j*EE;
    int p = (j + 3) & 3;
    const int* base = ei + (size_t)p*2*EE;
    int src = __ldg(&base[e]);
    int dst = __ldg(&base[EE + e]);
    int pos = atomicAdd(&g_cur[j*NN + dst], 1);
    g_esrc[pos] = src;
    g_enorm[pos] = __ldg(&g_dinv[j*NN + src]) * __ldg(&g_dinv[j*NN + dst]);
}

// ---------------- GCN GEMM: h = (emb*rels) @ W (FFMA2 packed over k) -------
__global__ __launch_bounds__(256) void k_gcn_gemm(
    const float* __restrict__ Wg, const float* __restrict__ rels)
{
    extern __shared__ float sm[];
    float* Wsm = sm;               // 64*128 float2 = 16384 floats
    float* Xsm = sm + 128*128;     // 64*128
    int j = blockIdx.y;
    int r0 = blockIdx.x * 64;
    int tid = threadIdx.x;

    for (int e = tid; e < 64*128; e += 256) {
        int kk = e >> 7, c = e & 127;
        ((float2*)Wsm)[e] = make_float2(Wg[(2*kk)*128 + c], Wg[(2*kk+1)*128 + c]);
    }
    const float* rrow = rels + j*DD;
    for (int e = tid; e < 64*128; e += 256) {
        int r = e >> 7, k = e & 127;
        int gr = r0 + r;
        Xsm[e] = (gr < NN) ? g_emb[((size_t)j*NN + gr)*DD + k] * __ldg(&rrow[k]) : 0.0f;
    }
    __syncthreads();

    int wid = tid >> 5, lane = tid & 31;
    ull acc2[8][4];
#pragma unroll
    for (int r = 0; r < 8; r++) { acc2[r][0]=0ull; acc2[r][1]=0ull; acc2[r][2]=0ull; acc2[r][3]=0ull; }
    const float* xb = Xsm + (wid*8)*128;
    const ull* wp = (const ull*)Wsm;
#pragma unroll 2
    for (int kk = 0; kk < 64; kk++) {
        ulonglong2 wa = *(const ulonglong2*)&wp[kk*128 + lane*4];
        ulonglong2 wb = *(const ulonglong2*)&wp[kk*128 + lane*4 + 2];
#pragma unroll
        for (int r = 0; r < 8; r++) {
            ull xv = *(const ull*)&xb[r*128 + 2*kk];
            FMA2(acc2[r][0], xv, wa.x); FMA2(acc2[r][1], xv, wa.y);
            FMA2(acc2[r][2], xv, wb.x); FMA2(acc2[r][3], xv, wb.y);
        }
    }
#pragma unroll
    for (int r = 0; r < 8; r++) {
        int gr = r0 + wid*8 + r;
        if (gr < NN) {
            float lo, hi, v[4];
#pragma unroll
            for (int c = 0; c < 4; c++) { UNPK(lo, hi, acc2[r][c]); v[c] = lo + hi; }
            *(float4*)&g_h[((size_t)j*NN + gr)*DD + lane*4] = make_float4(v[0], v[1], v[2], v[3]);
        }
    }
}

// ---------------- gather: agg = b + h[dst]*d2 + sum h[src]*norm ------------
__global__ __launch_bounds__(256) void k_gather(const float* __restrict__ bg) {
    int j = blockIdx.y;
    int wid = threadIdx.x >> 5, lane = threadIdx.x & 31;
    int dst = blockIdx.x*8 + wid;
    if (dst >= NN) return;
    int idx = j*NN + dst;
    int beg = __ldg(&g_off[idx]);
    int cnt = __ldg(&g_cnt[idx]);
    float dd = __ldg(&g_dinv[idx]);
    float d2 = dd*dd;

    float4 b4 = *(const float4*)&bg[lane*4];
    float4 hd = *(const float4*)&g_h[((size_t)idx)*DD + lane*4];
    float ax = b4.x + hd.x*d2, ay = b4.y + hd.y*d2;
    float az = b4.z + hd.z*d2, aw = b4.w + hd.w*d2;

    int t = 0;
    for (; t + 4 <= cnt; t += 4) {
        int s0 = __ldg(&g_esrc[beg + t]);
        int s1 = __ldg(&g_esrc[beg + t + 1]);
        int s2 = __ldg(&g_esrc[beg + t + 2]);
        int s3 = __ldg(&g_esrc[beg + t + 3]);
        float n0 = __ldg(&g_enorm[beg + t]);
        float n1 = __ldg(&g_enorm[beg + t + 1]);
        float n2 = __ldg(&g_enorm[beg + t + 2]);
        float n3 = __ldg(&g_enorm[beg + t + 3]);
        float4 h0 = *(const float4*)&g_h[((size_t)j*NN + s0)*DD + lane*4];
        float4 h1 = *(const float4*)&g_h[((size_t)j*NN + s1)*DD + lane*4];
        float4 h2 = *(const float4*)&g_h[((size_t)j*NN + s2)*DD + lane*4];
        float4 h3 = *(const float4*)&g_h[((size_t)j*NN + s3)*DD + lane*4];
        ax += h0.x*n0 + h1.x*n1 + h2.x*n2 + h3.x*n3;
        ay += h0.y*n0 + h1.y*n1 + h2.y*n2 + h3.y*n3;
        az += h0.z*n0 + h1.z*n1 + h2.z*n2 + h3.z*n3;
        aw += h0.w*n0 + h1.w*n1 + h2.w*n2 + h3.w*n3;
    }
    for (; t < cnt; t++) {
        int s0 = __ldg(&g_esrc[beg + t]);
        float n0 = __ldg(&g_enorm[beg + t]);
        float4 h0 = *(const float4*)&g_h[((size_t)j*NN + s0)*DD + lane*4];
        ax += h0.x*n0; ay += h0.y*n0; az += h0.z*n0; aw += h0.w*n0;
    }
    *(float4*)&g_agg[((size_t)idx)*DD + lane*4] = make_float4(ax, ay, az, aw);
}

// ---------------- BatchNorm ------------------------------------------------
__global__ void k_zero_stats() { int i = threadIdx.x; if (i < 4*DD*2) g_stats[i] = 0.f; }

__global__ void k_bn_stats(int chunk) {
    int j = blockIdx.y, c = threadIdx.x;
    int rs = blockIdx.x * chunk;
    int re = min(rs + chunk, NN);
    float s = 0.f, s2 = 0.f;
    const float* base = g_agg + (size_t)j*NE;
    for (int r = rs; r < re; r++) {
        float v = base[(size_t)r*DD + c];
        s += v; s2 += v*v;
    }
    atomicAdd(&g_stats[(j*DD + c)*2], s);
    atomicAdd(&g_stats[(j*DD + c)*2 + 1], s2);
}

__global__ void k_bn_finalize(const float* __restrict__ gamma, const float* __restrict__ beta) {
    int i = threadIdx.x;
    if (i < 4*DD) {
        int c = i & 127;
        float s = g_stats[i*2], s2 = g_stats[i*2 + 1];
        float mean = s / (float)NN;
        float var = s2 / (float)NN - mean*mean;
        float sc = __ldg(&gamma[c]) * rsqrtf(var + 1e-5f);
        g_bnp[i*2] = sc;
        g_bnp[i*2 + 1] = __ldg(&beta[c]) - mean*sc;
    }
}

__global__ void k_bn_apply() {
    long i = blockIdx.x*(long)blockDim.x + threadIdx.x;
    if (i >= 4l*NE) return;
    int c = (int)(i & 127);
    int j = (int)(i / NE);
    float v = g_agg[i];
    float sc = __ldg(&g_bnp[(j*DD + c)*2]);
    float sh = __ldg(&g_bnp[(j*DD + c)*2 + 1]);
    float y = v*sc + sh;
    y = (y > 0.f) ? y : 0.01f*y;
    g_emb[i] += y;
}

// ---------------- relation embedding update: r = r @ Wrt^T + brt -----------
__global__ void k_rels_update(const float* __restrict__ Wrt, const float* __restrict__ brt,
                              const float* __restrict__ rin, float* __restrict__ rout) {
    __shared__ float rs[4*DD];
    int tid = threadIdx.x;
    if (tid < 4*DD) rs[tid] = rin[tid];
    __syncthreads();
    if (tid < 4*DD) {
        int j = tid >> 7, k = tid & 127;
        float acc = __ldg(&brt[k]);
        const float* wr = Wrt + k*DD;
#pragma unroll 4
        for (int m = 0; m < DD; m++) acc += rs[j*DD + m] * __ldg(&wr[m]);
        rout[tid] = acc;
    }
}

// ---------------- fused QKV GEMM + attention -------------------------------
// block = 8 nodes, all 4 stack rows. qkv stays in smem; writes o to g_h.
// GEMM rows r = l*8 + n; X[r] = g_agg[mp[l]*NN + node]. FFMA2 inner loop.
#define QS 385
#define QKVS 388
__global__ __launch_bounds__(256) void k_qkv_attn(
    const float* __restrict__ Wg, const float* __restrict__ bg)
{
    extern __shared__ float sm[];
    float* Wsm = sm;                 // 64*QS float2 (reused as Qsm after GEMM)
    float* Xsm = sm + 64*QS*2;       // 32*128
    float* Qsm = sm;                 // 32 rows * QKVS (inside W region)
    const int mp[4] = {3, 0, 2, 1};
    int n0 = blockIdx.x * 8;
    int tid = threadIdx.x;

    for (int e = tid; e < 384*64; e += 256) {
        int c = e >> 6, kk = e & 63;
        float2 v = *(const float2*)&Wg[c*128 + 2*kk];
        ((float2*)Wsm)[kk*QS + c] = v;
    }
    for (int e = tid; e < 32*128; e += 256) {
        int r = e >> 7, k = e & 127;
        int l = r >> 3, n = r & 7;
        Xsm[e] = g_agg[((size_t)mp[l]*NN + n0 + n)*DD + k];
    }
    __syncthreads();

    int wid = tid >> 5, lane = tid & 31;
    ull acc2[4][12];
#pragma unroll
    for (int r = 0; r < 4; r++)
#pragma unroll
        for (int c = 0; c < 12; c++) acc2[r][c] = 0ull;
    const float* xb = Xsm + (wid*4)*128;
    const ull* wp = (const ull*)Wsm;
#pragma unroll 2
    for (int kk = 0; kk < 64; kk++) {
        ull wv[12];
#pragma unroll
        for (int p = 0; p < 3; p++)
#pragma unroll
            for (int c = 0; c < 4; c++)
                wv[p*4 + c] = wp[kk*QS + p*128 + lane*4 + c];
#pragma unroll
        for (int r = 0; r < 4; r++) {
            ull xv = *(const ull*)&xb[r*128 + 2*kk];
#pragma unroll
            for (int c = 0; c < 12; c++) FMA2(acc2[r][c], xv, wv[c]);
        }
    }
    __syncthreads();   // all W reads done; safe to overwrite with qkv

#pragma unroll
    for (int r = 0; r < 4; r++) {
        int row = wid*4 + r;
#pragma unroll
        for (int p = 0; p < 3; p++) {
            float4 b4 = *(const float4*)&bg[p*128 + lane*4];
            float lo, hi, v[4];
#pragma unroll
            for (int c = 0; c < 4; c++) { UNPK(lo, hi, acc2[r][p*4+c]); v[c] = lo + hi; }
            *(float4*)&Qsm[row*QKVS + p*128 + lane*4] =
                make_float4(v[0]+b4.x, v[1]+b4.y, v[2]+b4.z, v[3]+b4.w);
        }
    }
    __syncthreads();

    // attention: thread t<128 handles (node n, head h, stack row l)
    if (tid < 128) {
        int n = tid & 7, h = (tid >> 3) & 3, l = tid >> 5;
        const float scale = 0.17677669529663687f;   // 1/sqrt(32)
        const float* qp = &Qsm[(l*8+n)*QKVS + h*32];
        float q[32];
#pragma unroll
        for (int i = 0; i < 32; i++) q[i] = qp[i] * scale;
        float s[4]; float mx = -1e30f;
#pragma unroll
        for (int m = 0; m < 4; m++) {
            const float* kp = &Qsm[(m*8+n)*QKVS + 128 + h*32];
            float a = 0.f;
#pragma unroll
            for (int i = 0; i < 32; i++) a += q[i]*kp[i];
            s[m] = a; mx = fmaxf(mx, a);
        }
        float e[4]; float den = 0.f;
#pragma unroll
        for (int m = 0; m < 4; m++) { e[m] = expf(s[m] - mx); den += e[m]; }
        float inv = 1.0f/den;
        float o[32];
#pragma unroll
        for (int i = 0; i < 32; i++) o[i] = 0.f;
#pragma unroll
        for (int m = 0; m < 4; m++) {
            float a = e[m]*inv;
            const float* vp = &Qsm[(m*8+n)*QKVS + 256 + h*32];
#pragma unroll
            for (int i = 0; i < 32; i++) o[i] += a*vp[i];
        }
        float* op = g_h + ((size_t)l*NN + n0 + n)*DD + h*32;
#pragma unroll
        for (int i = 0; i < 8; i++)
            *(float4*)&op[i*4] = make_float4(o[i*4], o[i*4+1], o[i*4+2], o[i*4+3]);
    }
}

// ---------------- out-proj + alpha fusion (FFMA2, W^T pair layout) ---------
#define TS 129
__global__ __launch_bounds__(256) void k_outproj(
    const float* __restrict__ Wg, const float* __restrict__ bg,
    const float* __restrict__ alphas)
{
    extern __shared__ float sm[];
    float* Wsm = sm;              // 64*TS float2
    float* Xsm = sm + 64*TS*2;    // 64*128
    int l = blockIdx.y;
    const int mp[4] = {3, 0, 2, 1};
    int m = mp[l];
    int r0 = blockIdx.x * 64;
    int tid = threadIdx.x;

    for (int e = tid; e < 128*64; e += 256) {
        int c = e >> 6, kk = e & 63;
        float2 v = *(const float2*)&Wg[c*128 + 2*kk];
        ((float2*)Wsm)[kk*TS + c] = v;
    }
    for (int e = tid; e < 64*128; e += 256) {
        int r = e >> 7, k = e & 127;
        int gr = r0 + r;
        Xsm[e] = (gr < NN) ? g_h[((size_t)l*NN + gr)*DD + k] : 0.0f;
    }
    __syncthreads();

    int wid = tid >> 5, lane = tid & 31;
    ull acc2[8][4];
#pragma unroll
    for (int r = 0; r < 8; r++) { acc2[r][0]=0ull; acc2[r][1]=0ull; acc2[r][2]=0ull; acc2[r][3]=0ull; }
    const float* xb = Xsm + (wid*8)*128;
    const ull* wp = (const ull*)Wsm;
#pragma unroll 2
    for (int kk = 0; kk < 64; kk++) {
        ull w0 = wp[kk*TS + lane*4 + 0];
        ull w1 = wp[kk*TS + lane*4 + 1];
        ull w2 = wp[kk*TS + lane*4 + 2];
        ull w3 = wp[kk*TS + lane*4 + 3];
#pragma unroll
        for (int r = 0; r < 8; r++) {
            ull xv = *(const ull*)&xb[r*128 + 2*kk];
            FMA2(acc2[r][0], xv, w0); FMA2(acc2[r][1], xv, w1);
            FMA2(acc2[r][2], xv, w2); FMA2(acc2[r][3], xv, w3);
        }
    }
    float a = __ldg(&alphas[l]);
    float na = 1.0f - a;
    float4 b4 = *(const float4*)&bg[lane*4];
#pragma unroll
    for (int r = 0; r < 8; r++) {
        int gr = r0 + wid*8 + r;
        if (gr < NN) {
            float4 s4 = *(const float4*)&g_agg[((size_t)m*NN + gr)*DD + lane*4];
            float lo, hi, v[4];
#pragma unroll
            for (int c = 0; c < 4; c++) { UNPK(lo, hi, acc2[r][c]); v[c] = lo + hi; }
            float4 f4 = make_float4(a*(v[0] + b4.x) + na*s4.x,
                                    a*(v[1] + b4.y) + na*s4.y,
                                    a*(v[2] + b4.z) + na*s4.z,
                                    a*(v[3] + b4.w) + na*s4.w);
            *(float4*)&g_emb[((size_t)l*NN + gr)*DD + lane*4] = f4;
        }
    }
}

// ---------------- fusion score (FFMA2, W^T pair layout) --------------------
__global__ __launch_bounds__(256) void k_score(
    const float* __restrict__ Wg, const float* __restrict__ bg,
    const float* __restrict__ qv)
{
    extern __shared__ float sm[];
    float* Wsm = sm;              // 64*TS float2
    float* Xsm = sm + 64*TS*2;    // 64*128
    __shared__ float wsum[8];
    int l = blockIdx.y;
    const int slotmap[4] = {0, 1, 3, 2};
    int r0 = blockIdx.x * 64;
    int tid = threadIdx.x;

    for (int e = tid; e < 128*64; e += 256) {
        int c = e >> 6, kk = e & 63;
        float2 v = *(const float2*)&Wg[c*128 + 2*kk];
        ((float2*)Wsm)[kk*TS + c] = v;
    }
    for (int e = tid; e < 64*128; e += 256) {
        int r = e >> 7, k = e & 127;
        int gr = r0 + r;
        Xsm[e] = (gr < NN) ? g_emb[((size_t)l*NN + gr)*DD + k] : 0.0f;
    }
    __syncthreads();

    int wid = tid >> 5, lane = tid & 31;
    ull acc2[8][4];
#pragma unroll
    for (int r = 0; r < 8; r++) { acc2[r][0]=0ull; acc2[r][1]=0ull; acc2[r][2]=0ull; acc2[r][3]=0ull; }
    const float* xb = Xsm + (wid*8)*128;
    const ull* wp = (const ull*)Wsm;
#pragma unroll 2
    for (int kk = 0; kk < 64; kk++) {
        ull w0 = wp[kk*TS + lane*4 + 0];
        ull w1 = wp[kk*TS + lane*4 + 1];
        ull w2 = wp[kk*TS + lane*4 + 2];
        ull w3 = wp[kk*TS + lane*4 + 3];
#pragma unroll
        for (int r = 0; r < 8; r++) {
            ull xv = *(const ull*)&xb[r*128 + 2*kk];
            FMA2(acc2[r][0], xv, w0); FMA2(acc2[r][1], xv, w1);
            FMA2(acc2[r][2], xv, w2); FMA2(acc2[r][3], xv, w3);
        }
    }
    float4 b4 = *(const float4*)&bg[lane*4];
    float4 q4 = *(const float4*)&qv[lane*4];
    float lsum = 0.f;
#pragma unroll
    for (int r = 0; r < 8; r++) {
        int gr = r0 + wid*8 + r;
        if (gr < NN) {
            float lo, hi, v[4];
#pragma unroll
            for (int c = 0; c < 4; c++) { UNPK(lo, hi, acc2[r][c]); v[c] = lo + hi; }
            float v0 = v[0] + b4.x; v0 = (v0 > 0.f) ? v0 : 0.01f*v0;
            float v1 = v[1] + b4.y; v1 = (v1 > 0.f) ? v1 : 0.01f*v1;
            float v2 = v[2] + b4.z; v2 = (v2 > 0.f) ? v2 : 0.01f*v2;
            float v3 = v[3] + b4.w; v3 = (v3 > 0.f) ? v3 : 0.01f*v3;
            lsum += v0*q4.x + v1*q4.y + v2*q4.z + v3*q4.w;
        }
    }
#pragma unroll
    for (int o = 16; o > 0; o >>= 1) lsum += __shfl_xor_sync(0xffffffffu, lsum, o);
    if (lane == 0) wsum[wid] = lsum;
    __syncthreads();
    if (tid == 0) {
        float tot = 0.f;
#pragma unroll
        for (int i = 0; i < 8; i++) tot += wsum[i];
        atomicAdd(&g_score[slotmap[l]], tot);
    }
}

__global__ void k_softmax_w() {
    if (threadIdx.x == 0 && blockIdx.x == 0) {
        float s[4]; float mx = -1e30f;
        for (int i = 0; i < 4; i++) { s[i] = g_score[i] / (float)NN; mx = fmaxf(mx, s[i]); }
        float e[4]; float den = 0.f;
        for (int i = 0; i < 4; i++) { e[i] = expf(s[i] - mx); den += e[i]; }
        for (int i = 0; i < 4; i++) g_w[i] = e[i] / den;
    }
}

// ---------------- final region + 5 outputs ---------------------------------
__global__ void k_final(float* __restrict__ out) {
    int i = blockIdx.x * blockDim.x + threadIdx.x;
    if (i >= NE) return;
    int c = i & 127;
    float f0 = g_emb[i], f1 = g_emb[NE + i], f2 = g_emb[2*NE + i], f3 = g_emb[3*NE + i];
    float w0 = __ldg(&g_w[0]), w1 = __ldg(&g_w[1]), w2 = __ldg(&g_w[2]), w3 = __ldg(&g_w[3]);
    float region = w0*f0 + w1*f1 + w2*f3 + w3*f2;
    const float* rf = g_rels[1];   // final rels after 3 ping-pong updates
    out[i]        = region;
    out[NE + i]   = region * __ldg(&rf[3*DD + c]);
    out[2*NE + i] = region * __ldg(&rf[0*DD + c]);
    out[3*NE + i] = region * __ldg(&rf[1*DD + c]);
    out[4*NE + i] = region * __ldg(&rf[2*DD + c]);
}

// ---------------- host launcher --------------------------------------------
extern "C" void kernel_launch(void* const* d_in, const int* in_sizes, int n_in,
                              void* d_out, int out_size) {
    const float* features   = (const float*)d_in[0];
    const float* rel_emb    = (const float*)d_in[1];
    const int*   edge_index = (const int*)  d_in[2];
    const float* W_gcn      = (const float*)d_in[3];
    const float* b_gcn      = (const float*)d_in[4];
    const float* bn_gamma   = (const float*)d_in[5];
    const float* bn_beta    = (const float*)d_in[6];
    const float* W_rt       = (const float*)d_in[7];
    const float* b_rt       = (const float*)d_in[8];
    const float* attn_w_in  = (const float*)d_in[9];
    const float* attn_b_in  = (const float*)d_in[10];
    const float* attn_w_out = (const float*)d_in[11];
    const float* attn_b_out = (const float*)d_in[12];
    const float* alphas     = (const float*)d_in[13];
    const float* fusion_q   = (const float*)d_in[14];
    const float* fusion_w   = (const float*)d_in[15];
    const float* fusion_b   = (const float*)d_in[16];
    float* out = (float*)d_out;

    const int GCN_SMEM  = (64*128*2 + 64*128) * 4;     // 96 KB
    const int QKV_SMEM  = (64*QS*2 + 32*128) * 4;      // ~213 KB
    const int T_SMEM    = (64*TS*2 + 64*128) * 4;      // ~98.5 KB
    cudaFuncSetAttribute(k_gcn_gemm, cudaFuncAttributeMaxDynamicSharedMemorySize, GCN_SMEM);
    cudaFuncSetAttribute(k_qkv_attn, cudaFuncAttributeMaxDynamicSharedMemorySize, QKV_SMEM);
    cudaFuncSetAttribute(k_outproj,  cudaFuncAttributeMaxDynamicSharedMemorySize, T_SMEM);
    cudaFuncSetAttribute(k_score,    cudaFuncAttributeMaxDynamicSharedMemorySize, T_SMEM);

    dim3 ggrid((NN + 63)/64, 4);
    dim3 agrid((NN + 7)/8, 4);
    dim3 bngrid(128, 4);
    int bnchunk = (NN + 127)/128;

    float* r0p; float* r1p;
    cudaGetSymbolAddress((void**)&r0p, g_rels);   // buf0
    r1p = r0p + 4*DD;                             // buf1

    const float* rin[3]  = { r0p, r1p, r0p };
    float*       rout[3] = { r1p, r0p, r1p };

    // init + CSR build. Launch order puts the layer-0 GCN GEMM at launch
    // index 5 so ncu's "-s 5 -c 1" window profiles the hot kernel.
    k_init_emb<<<(NE + 255)/256, 256>>>(features);                 // 0
    k_init_small<<<(NB4 + 255)/256, 256>>>(rel_emb);               // 1
    k_hist<<<(4*EE + 255)/256, 256>>>(edge_index);                 // 2
    k_scan1<<<SCAN_BLOCKS, 1024>>>();                              // 3
    k_scan2<<<1, 32>>>();                                          // 4
    k_gcn_gemm<<<ggrid, 256, GCN_SMEM>>>(W_gcn, rin[0]);           // 5 <- profiled
    k_scan3<<<(NB4 + 255)/256, 256>>>();                           // 6
    k_reorder<<<(4*EE + 255)/256, 256>>>(edge_index);              // 7

    for (int i = 0; i < 2; i++) {
        if (i > 0) k_gcn_gemm<<<ggrid, 256, GCN_SMEM>>>(W_gcn + i*DD*DD, rin[i]);
        k_gather<<<agrid, 256>>>(b_gcn + i*DD);
        k_zero_stats<<<1, 1024>>>();
        k_bn_stats<<<bngrid, 128>>>(bnchunk);
        k_bn_finalize<<<1, 512>>>(bn_gamma + i*DD, bn_beta + i*DD);
        k_bn_apply<<<(4*NE + 255)/256, 256>>>();
        k_rels_update<<<1, 512>>>(W_rt + i*DD*DD, b_rt + i*DD, rin[i], rout[i]);
    }
    k_gcn_gemm<<<ggrid, 256, GCN_SMEM>>>(W_gcn + 2*DD*DD, rin[2]);
    k_gather<<<agrid, 256>>>(b_gcn + 2*DD);
    k_rels_update<<<1, 512>>>(W_rt + 2*DD*DD, b_rt + 2*DD, rin[2], rout[2]);

    // fused MHA + fusion
    k_qkv_attn<<<NN/8, 256, QKV_SMEM>>>(attn_w_in, attn_b_in);
    k_outproj<<<ggrid, 256, T_SMEM>>>(attn_w_out, attn_b_out, alphas);
    k_score<<<ggrid, 256, T_SMEM>>>(fusion_w, fusion_b, fusion_q);
    k_softmax_w<<<1, 32>>>();
    k_final<<<(NE + 255)/256, 256>>>(out);
}